// round 5
// baseline (speedup 1.0000x reference)
#include <cuda_runtime.h>
#include <math.h>

#define Bv   8
#define Nv   2000
#define Cv   91
#define FG   90
#define NIMG (Nv*FG)      /* 180000 candidates per image */
#define TOPK 2048
#define DETS 100
#define REGW (Cv*4)       /* 364 floats per proposal row */
#define NWORDS 32         /* 2048/64 */
#define NBINS 65536
#define GCAP  16384

typedef unsigned long long u64;

__device__ float g_scores[Bv*NIMG];             // masked scores (valid ? score : -1)
__device__ unsigned g_hist[Bv*NBINS];
__device__ unsigned g_thr[Bv];
__device__ unsigned g_gcnt[Bv];
__device__ u64 g_cand[Bv*GCAP];
__device__ u64 g_keys[Bv*TOPK];                 // sorted (score<<32 | ~idx) per image
__device__ float4 g_cbox[Bv*TOPK];              // clipped boxes
__device__ float4 g_obox[Bv*TOPK];              // offset boxes
__device__ float  g_cscore[Bv*TOPK];
__device__ int    g_clabel[Bv*TOPK];
__device__ u64 g_valid[Bv*NWORDS];
__device__ u64 g_mask[Bv*TOPK*NWORDS];          // 4 MB suppression matrix

// ---------- order-preserving float<->uint ----------
__device__ __forceinline__ unsigned orderf(float f) {
    unsigned u = __float_as_uint(f);
    return (u & 0x80000000u) ? ~u : (u | 0x80000000u);
}
__device__ __forceinline__ float unorderf(unsigned u) {
    u = (u & 0x80000000u) ? (u ^ 0x80000000u) : ~u;
    return __uint_as_float(u);
}

struct Box { float x1, y1, x2, y2; };

// Replicates the JAX decode + clip exactly (fp32 op sequence).
__device__ __forceinline__ Box decode_one(float4 r, float x1, float y1, float x2, float y2) {
    const float CLIPV = 4.135166556742356f;   // log(1000/16) as f32
    float w  = x2 - x1, h = y2 - y1;
    float cx = x1 + 0.5f * w, cy = y1 + 0.5f * h;
    float dx = r.x / 10.0f, dy = r.y / 10.0f;
    float dw = fminf(r.z / 5.0f, CLIPV);
    float dh = fminf(r.w / 5.0f, CLIPV);
    float pcx = dx * w + cx, pcy = dy * h + cy;
    float pw  = expf(dw) * w, ph = expf(dh) * h;
    Box o;
    o.x1 = pcx - 0.5f * pw; o.y1 = pcy - 0.5f * ph;
    o.x2 = pcx + 0.5f * pw; o.y2 = pcy + 0.5f * ph;
    o.x1 = fminf(fmaxf(o.x1, 0.0f), 1333.0f);
    o.y1 = fminf(fmaxf(o.y1, 0.0f),  800.0f);
    o.x2 = fminf(fmaxf(o.x2, 0.0f), 1333.0f);
    o.y2 = fminf(fmaxf(o.y2, 0.0f),  800.0f);
    return o;
}

// =====================================================================
// K0: zero the histogram + gather counters (graph-replay determinism)
// =====================================================================
__global__ void zero_kernel() {
    unsigned i = blockIdx.x * 1024u + threadIdx.x;
    if (i < Bv * NBINS) g_hist[i] = 0u;
    if (i < Bv) g_gcnt[i] = 0u;
}

// =====================================================================
// K1: one warp per proposal. Softmax over 91 classes, decode fg boxes,
// write masked score, histogram valid scores (top-16 ordered bits).
// =====================================================================
__global__ void score_kernel(const float* __restrict__ logits,
                             const float* __restrict__ reg,
                             const float* __restrict__ props) {
    int warp = (blockIdx.x * blockDim.x + threadIdx.x) >> 5;
    int lane = threadIdx.x & 31;
    if (warp >= Bv * Nv) return;

    const float* lrow = logits + (size_t)warp * Cv;
    float l0 = lrow[lane];
    float l1 = lrow[32 + lane];
    float l2 = (64 + lane < Cv) ? lrow[64 + lane] : -3.402823466e38f;
    float m = fmaxf(l0, fmaxf(l1, l2));
    #pragma unroll
    for (int o = 16; o; o >>= 1) m = fmaxf(m, __shfl_xor_sync(0xFFFFFFFFu, m, o));
    float e0 = expf(l0 - m), e1 = expf(l1 - m);
    float e2 = (64 + lane < Cv) ? expf(l2 - m) : 0.0f;
    float s = e0 + e1 + e2;
    #pragma unroll
    for (int o = 16; o; o >>= 1) s += __shfl_xor_sync(0xFFFFFFFFu, s, o);

    int b = warp / Nv, p = warp % Nv;
    const float* pb = props + (size_t)warp * 4;
    float px1 = pb[0], py1 = pb[1], px2 = pb[2], py2 = pb[3];

    float* outsc = g_scores + (size_t)b * NIMG + (size_t)p * FG;
    const float* rrow = reg + (size_t)warp * REGW;

    float ev[3] = {e0, e1, e2};
    #pragma unroll
    for (int k = 0; k < 3; k++) {
        int c = lane + 32 * k;
        if (c >= 1 && c <= FG) {
            float sc = ev[k] / s;
            float4 r = *reinterpret_cast<const float4*>(rrow + c * 4);
            Box bx = decode_one(r, px1, py1, px2, py2);
            float ws = bx.x2 - bx.x1, hs = bx.y2 - bx.y1;
            bool valid = (sc > 0.05f) && (ws >= 0.01f) && (hs >= 0.01f);
            float msc = valid ? sc : -1.0f;
            outsc[c - 1] = msc;
            if (valid)
                atomicAdd(&g_hist[b * NBINS + (orderf(msc) >> 16)], 1u);
        }
    }
}

// =====================================================================
// K2a: per image, find threshold bin. Warp-per-chunk coalesced sums,
// then selected chunk staged to smem before serial scan.
// =====================================================================
__global__ void __launch_bounds__(1024, 1) findthr_kernel() {
    int b = blockIdx.x, tid = threadIdx.x;
    int warp = tid >> 5, lane = tid & 31;
    __shared__ unsigned csum[256];
    __shared__ unsigned bins[256];
    __shared__ int sel_c;
    __shared__ unsigned sel_acc;
    const unsigned* h = g_hist + b * NBINS;

    for (int c = warp; c < 256; c += 32) {
        unsigned s = 0;
        for (int j = lane; j < 256; j += 32) s += h[c * 256 + j];
        #pragma unroll
        for (int o = 16; o; o >>= 1) s += __shfl_xor_sync(0xFFFFFFFFu, s, o);
        if (lane == 0) csum[c] = s;
    }
    __syncthreads();
    if (tid == 0) {
        unsigned acc = 0;
        int c = 255;
        for (; c >= 0; c--) {
            if (acc + csum[c] >= TOPK) break;
            acc += csum[c];
        }
        sel_c = c; sel_acc = acc;
    }
    __syncthreads();
    int c = sel_c;
    if (c >= 0)
        for (int j = tid; j < 256; j += 1024) bins[j] = h[c * 256 + j];
    __syncthreads();
    if (tid == 0) {
        unsigned thr = 0;
        if (c >= 0) {
            unsigned acc = sel_acc;
            int bin = 255;
            for (; bin >= 0; bin--) {
                acc += bins[bin];
                if (acc >= TOPK) break;
            }
            thr = (unsigned)(c * 256 + (bin >= 0 ? bin : 0));
        }
        g_thr[b] = thr;
    }
}

// =====================================================================
// K2b: gather composite keys with bin >= thr (float4-vectorized).
// =====================================================================
__global__ void gather_kernel() {
    int b   = blockIdx.x >> 5;
    int bi  = blockIdx.x & 31;
    int tid = threadIdx.x;
    const float4* sc4 = reinterpret_cast<const float4*>(g_scores + (size_t)b * NIMG);
    unsigned thr = g_thr[b];
    for (int i4 = bi * 256 + tid; i4 < NIMG / 4; i4 += 32 * 256) {
        float4 v = sc4[i4];
        float vs[4] = {v.x, v.y, v.z, v.w};
        #pragma unroll
        for (int c = 0; c < 4; c++) {
            unsigned u = orderf(vs[c]);
            if ((u >> 16) >= thr) {
                unsigned i = (unsigned)(i4 * 4 + c);
                unsigned pos = atomicAdd(&g_gcnt[b], 1u);
                if (pos < GCAP)
                    g_cand[(size_t)b * GCAP + pos] =
                        ((u64)u << 32) | (u64)(0xFFFFFFFFu - i);
            }
        }
    }
}

// =====================================================================
// K2c: per-image bitonic sort (desc) of gathered keys, emit top-2048.
// =====================================================================
__global__ void __launch_bounds__(1024, 1) sort_kernel() {
    extern __shared__ u64 skeys[];
    int b = blockIdx.x, tid = threadIdx.x;
    unsigned cnt = g_gcnt[b];
    if (cnt > GCAP) cnt = GCAP;
    unsigned P2 = 2048;
    while (P2 < cnt) P2 <<= 1;
    for (unsigned i = tid; i < P2; i += 1024)
        skeys[i] = (i < cnt) ? g_cand[(size_t)b * GCAP + i] : 0ull;
    __syncthreads();
    for (unsigned kk = 2; kk <= P2; kk <<= 1) {
        for (unsigned j = kk >> 1; j; j >>= 1) {
            for (unsigned i = tid; i < P2; i += 1024) {
                unsigned p = i ^ j;
                if (p > i) {
                    bool desc = ((i & kk) == 0);
                    u64 a = skeys[i], c = skeys[p];
                    if (desc ? (a < c) : (a > c)) { skeys[i] = c; skeys[p] = a; }
                }
            }
            __syncthreads();
        }
    }
    for (int i = tid; i < TOPK; i += 1024) g_keys[(size_t)b * TOPK + i] = skeys[i];
}

// =====================================================================
// K3a: one block per image. Decode candidates, class offsets, valid
// bitmask; stage everything to gmem for the mask/reduce kernels.
// =====================================================================
__global__ void __launch_bounds__(1024, 1) prep_kernel(const float* __restrict__ reg,
                                                       const float* __restrict__ props) {
    __shared__ float4 sbox[TOPK];
    __shared__ int    slab[TOPK];
    __shared__ float  sred[33];
    __shared__ u64    svalid[NWORDS];

    int b   = blockIdx.x;
    int tid = threadIdx.x;
    if (tid < NWORDS) svalid[tid] = 0ull;
    __syncthreads();

    float lmax = -3.402823466e38f;
    for (int r = tid; r < TOPK; r += 1024) {
        u64 key = g_keys[(size_t)b * TOPK + r];
        unsigned idx = 0xFFFFFFFFu - (unsigned)(key & 0xFFFFFFFFull);
        if (idx >= NIMG) idx = NIMG - 1;     // safety clamp (padding)
        float score  = unorderf((unsigned)(key >> 32));
        int p = idx / FG, cls = (int)(idx % FG) + 1;
        const float* pb = props + ((size_t)b * Nv + p) * 4;
        float4 rr = *reinterpret_cast<const float4*>(reg + ((size_t)b * Nv + p) * REGW + cls * 4);
        Box bx = decode_one(rr, pb[0], pb[1], pb[2], pb[3]);
        sbox[r] = make_float4(bx.x1, bx.y1, bx.x2, bx.y2);
        slab[r] = cls;
        g_cscore[(size_t)b * TOPK + r] = score;
        if (score > 0.0f)
            atomicOr(&svalid[r >> 6], 1ull << (r & 63));
        lmax = fmaxf(lmax, fmaxf(fmaxf(bx.x1, bx.y1), fmaxf(bx.x2, bx.y2)));
    }
    #pragma unroll
    for (int o = 16; o; o >>= 1) lmax = fmaxf(lmax, __shfl_xor_sync(0xFFFFFFFFu, lmax, o));
    if ((tid & 31) == 0) sred[tid >> 5] = lmax;
    __syncthreads();
    if (tid < 32) {
        float v = sred[tid];
        #pragma unroll
        for (int o = 16; o; o >>= 1) v = fmaxf(v, __shfl_xor_sync(0xFFFFFFFFu, v, o));
        if (tid == 0) sred[32] = v;
    }
    __syncthreads();
    float step = sred[32] + 1.0f;

    for (int r = tid; r < TOPK; r += 1024) {
        float off = (float)slab[r] * step;
        float4 cb = sbox[r];
        g_cbox[(size_t)b * TOPK + r]   = cb;
        g_obox[(size_t)b * TOPK + r]   = make_float4(cb.x + off, cb.y + off, cb.z + off, cb.w + off);
        g_clabel[(size_t)b * TOPK + r] = slab[r];
    }
    if (tid < NWORDS) g_valid[b * NWORDS + tid] = svalid[tid];
}

// =====================================================================
// K3b: suppression bitmask. Bv*128 blocks (16-row tiles), 256 thr.
// Division replaced by a band test; exact div only in the ambiguous
// band (bit-exact). Sub-diagonal words never written (zero-init).
// =====================================================================
__global__ void __launch_bounds__(256, 5) mask_kernel() {
    __shared__ float4 ob[TOPK];      // 32KB offset boxes
    __shared__ float  ar[TOPK];      // 8KB areas

    int b    = blockIdx.x >> 7;
    int tile = blockIdx.x & 127;
    int tid  = threadIdx.x;
    int rowbase = tile * 16;
    int wmin = rowbase >> 6;
    int lo   = wmin << 6;

    for (int i = lo + tid; i < TOPK; i += 256) {
        float4 v = g_obox[(size_t)b * TOPK + i];
        ob[i] = v;
        ar[i] = (v.z - v.x) * (v.w - v.y);
    }
    __syncthreads();

    int w = tid & 31;
    if (w < wmin) return;
    int r0 = rowbase + (tid >> 5) * 2;

    float4 rb0 = ob[r0],     rb1 = ob[r0 + 1];
    float  aa0 = ar[r0],     aa1 = ar[r0 + 1];
    u64 acc0 = 0ull, acc1 = 0ull;

    #pragma unroll 4
    for (int jj = 0; jj < 64; jj++) {
        int j = w * 64 + jj;
        float4 bj = ob[j];
        float bar = ar[j];
        {
            float ltx = fmaxf(rb0.x, bj.x), lty = fmaxf(rb0.y, bj.y);
            float rbx = fminf(rb0.z, bj.z), rby = fminf(rb0.w, bj.w);
            float ww  = fmaxf(rbx - ltx, 0.0f), hh = fmaxf(rby - lty, 0.0f);
            float inter = ww * hh;
            float U = (aa0 + bar) - inter;
            float hU = 0.5f * U;
            bool sup;
            if (inter > hU * 1.000001f)       sup = true;
            else if (inter < hU * 0.999999f)  sup = false;
            else                               sup = (inter / U) > 0.5f;
            if (sup && (j > r0)) acc0 |= (1ull << jj);
        }
        {
            float ltx = fmaxf(rb1.x, bj.x), lty = fmaxf(rb1.y, bj.y);
            float rbx = fminf(rb1.z, bj.z), rby = fminf(rb1.w, bj.w);
            float ww  = fmaxf(rbx - ltx, 0.0f), hh = fmaxf(rby - lty, 0.0f);
            float inter = ww * hh;
            float U = (aa1 + bar) - inter;
            float hU = 0.5f * U;
            bool sup;
            if (inter > hU * 1.000001f)       sup = true;
            else if (inter < hU * 0.999999f)  sup = false;
            else                               sup = (inter / U) > 0.5f;
            if (sup && (j > r0 + 1)) acc1 |= (1ull << jj);
        }
    }
    g_mask[((size_t)b * TOPK + r0)     * NWORDS + w] = acc0;
    g_mask[((size_t)b * TOPK + r0 + 1) * NWORDS + w] = acc1;
}

// =====================================================================
// K3c: serial reduce + emission. 1024 threads/image: warps 1-31 stream
// the mask into a 2x64KB smem ring (256-row batches); warp 0 runs the
// greedy reduce in 64-row windows reading smem, then emits top-100.
// =====================================================================
#define BATCH_ROWS 256
#define BATCH_WORDS (BATCH_ROWS*NWORDS)   /* 8192 u64 = 64KB */

__global__ void __launch_bounds__(1024, 1) reduce_emit_kernel(float* __restrict__ out) {
    extern __shared__ u64 sbuf[];         // 2 * BATCH_WORDS
    int b    = blockIdx.x;
    int tid  = threadIdx.x;
    int lane = tid & 31;
    int warp = tid >> 5;
    const u64* mbase = g_mask + (size_t)b * TOPK * NWORDS;

    // preload batch 0 (all threads)
    for (int i = tid; i < BATCH_WORDS; i += 1024) sbuf[i] = mbase[i];
    __syncthreads();

    u64 vw = 0, supp = 0;
    if (warp == 0) vw = g_valid[b * NWORDS + lane];

    const int NBATCH = TOPK / BATCH_ROWS;   // 8
    for (int bt = 0; bt < NBATCH; bt++) {
        u64* curb = sbuf + (bt & 1) * BATCH_WORDS;
        u64* nxtb = sbuf + ((bt + 1) & 1) * BATCH_WORDS;
        if (warp != 0 && bt + 1 < NBATCH) {
            const u64* src = mbase + (size_t)(bt + 1) * BATCH_WORDS;
            for (int i = tid - 32; i < BATCH_WORDS; i += 992) nxtb[i] = src[i];
        }
        if (warp == 0) {
            #pragma unroll
            for (int win = 0; win < BATCH_ROWS / 64; win++) {   // 4 windows of 64
                int owner = bt * 4 + win;                        // word index of this window
                u64 kept = 0ull;
                if (lane == owner) {
                    u64 w = vw & ~supp;
                    while (w) {
                        int k = __ffsll(w) - 1;
                        kept |= (1ull << k);
                        u64 mk = curb[(win * 64 + k) * NWORDS + owner];
                        w &= ~(mk | (1ull << k));
                    }
                }
                unsigned klo = (unsigned)kept, khi = (unsigned)(kept >> 32);
                klo = __shfl_sync(0xFFFFFFFFu, klo, owner);
                khi = __shfl_sync(0xFFFFFFFFu, khi, owner);
                kept = ((u64)khi << 32) | (u64)klo;
                u64 t = 0ull, kk = kept;
                while (kk) {
                    int k = __ffsll(kk) - 1;
                    kk &= kk - 1;
                    t |= curb[(win * 64 + k) * NWORDS + lane];
                }
                supp |= t;
            }
        }
        __syncthreads();
    }

    if (warp == 0) {
        u64 keep = vw & ~supp;

        int cnt = __popcll(keep);
        int inc = cnt;
        #pragma unroll
        for (int o = 1; o < 32; o <<= 1) {
            int v = __shfl_up_sync(0xFFFFFFFFu, inc, o);
            if (lane >= o) inc += v;
        }
        int excl  = inc - cnt;
        int total = __shfl_sync(0xFFFFFFFFu, inc, 31);

        float* oboxes  = out;                     // [B,100,4]
        float* oscores = out + Bv * DETS * 4;     // [B,100]
        float* olabels = out + Bv * DETS * 5;     // [B,100]

        for (int k = 0; k < 64; k++) {
            int r = lane * 64 + k;
            u64 below = (k == 0) ? 0ull : (keep & ((1ull << k) - 1ull));
            int kb   = excl + __popcll(below);
            int kp   = (int)((keep >> k) & 1ull);
            int slot = kp ? kb : total + (r - kb);
            if (slot < DETS) {
                float4 cb = g_cbox[(size_t)b * TOPK + r];
                float* obp = oboxes + ((size_t)b * DETS + slot) * 4;
                obp[0] = cb.x; obp[1] = cb.y; obp[2] = cb.z; obp[3] = cb.w;
                oscores[b * DETS + slot] = kp ? g_cscore[(size_t)b * TOPK + r] : -1.0f;
                olabels[b * DETS + slot] = (float)g_clabel[(size_t)b * TOPK + r];
            }
        }
    }
}

extern "C" void kernel_launch(void* const* d_in, const int* in_sizes, int n_in,
                              void* d_out, int out_size) {
    const float* logits = (const float*)d_in[0];   // [16000, 91]
    const float* reg    = (const float*)d_in[1];   // [16000, 364]
    const float* props  = (const float*)d_in[2];   // [8, 2000, 4]
    float* out = (float*)d_out;

    zero_kernel<<<(Bv * NBINS + 1023) / 1024, 1024>>>();
    score_kernel<<<(Bv * Nv + 7) / 8, 256>>>(logits, reg, props);
    findthr_kernel<<<Bv, 1024>>>();
    gather_kernel<<<Bv * 32, 256>>>();
    cudaFuncSetAttribute(sort_kernel, cudaFuncAttributeMaxDynamicSharedMemorySize,
                         GCAP * (int)sizeof(u64));
    sort_kernel<<<Bv, 1024, GCAP * sizeof(u64)>>>();
    prep_kernel<<<Bv, 1024>>>(reg, props);
    mask_kernel<<<Bv * 128, 256>>>();
    cudaFuncSetAttribute(reduce_emit_kernel, cudaFuncAttributeMaxDynamicSharedMemorySize,
                         2 * BATCH_WORDS * (int)sizeof(u64));
    reduce_emit_kernel<<<Bv, 1024, 2 * BATCH_WORDS * sizeof(u64)>>>(out);
}

// round 7
// speedup vs baseline: 1.7417x; 1.7417x over previous
#include <cuda_runtime.h>
#include <math.h>

#define Bv   8
#define Nv   2000
#define Cv   91
#define FG   90
#define NIMG (Nv*FG)      /* 180000 candidates per image */
#define TOPK 2048
#define DETS 100
#define REGW (Cv*4)       /* 364 floats per proposal row */
#define NWORDS 32         /* 2048/64 */
#define NBINS 65536
#define GCAP  16384

typedef unsigned long long u64;

__device__ float g_scores[Bv*NIMG];             // masked scores (valid ? score : -1)
__device__ unsigned g_hist[Bv*NBINS];
__device__ unsigned g_thr[Bv];
__device__ unsigned g_gcnt[Bv];
__device__ u64 g_cand[Bv*GCAP];
__device__ float4 g_cbox[Bv*TOPK];              // clipped boxes
__device__ float4 g_obox[Bv*TOPK];              // offset boxes
__device__ float  g_cscore[Bv*TOPK];
__device__ int    g_clabel[Bv*TOPK];
__device__ u64 g_valid[Bv*NWORDS];
__device__ u64 g_mask[Bv*TOPK*NWORDS];          // 4 MB suppression matrix

// ---------- order-preserving float<->uint ----------
__device__ __forceinline__ unsigned orderf(float f) {
    unsigned u = __float_as_uint(f);
    return (u & 0x80000000u) ? ~u : (u | 0x80000000u);
}
__device__ __forceinline__ float unorderf(unsigned u) {
    u = (u & 0x80000000u) ? (u ^ 0x80000000u) : ~u;
    return __uint_as_float(u);
}

struct Box { float x1, y1, x2, y2; };

// Replicates the JAX decode + clip exactly (fp32 op sequence).
__device__ __forceinline__ Box decode_one(float4 r, float x1, float y1, float x2, float y2) {
    const float CLIPV = 4.135166556742356f;   // log(1000/16) as f32
    float w  = x2 - x1, h = y2 - y1;
    float cx = x1 + 0.5f * w, cy = y1 + 0.5f * h;
    float dx = r.x / 10.0f, dy = r.y / 10.0f;
    float dw = fminf(r.z / 5.0f, CLIPV);
    float dh = fminf(r.w / 5.0f, CLIPV);
    float pcx = dx * w + cx, pcy = dy * h + cy;
    float pw  = expf(dw) * w, ph = expf(dh) * h;
    Box o;
    o.x1 = pcx - 0.5f * pw; o.y1 = pcy - 0.5f * ph;
    o.x2 = pcx + 0.5f * pw; o.y2 = pcy + 0.5f * ph;
    o.x1 = fminf(fmaxf(o.x1, 0.0f), 1333.0f);
    o.y1 = fminf(fmaxf(o.y1, 0.0f),  800.0f);
    o.x2 = fminf(fmaxf(o.x2, 0.0f), 1333.0f);
    o.y2 = fminf(fmaxf(o.y2, 0.0f),  800.0f);
    return o;
}

// =====================================================================
// K0: zero the histogram + gather counters (graph-replay determinism)
// =====================================================================
__global__ void zero_kernel() {
    unsigned i = blockIdx.x * 1024u + threadIdx.x;
    if (i < Bv * NBINS) g_hist[i] = 0u;
    if (i < Bv) g_gcnt[i] = 0u;
}

// =====================================================================
// K1: one warp per proposal. Softmax over 91 classes, decode fg boxes,
// write masked score, histogram valid scores (top-16 ordered bits).
// =====================================================================
__global__ void score_kernel(const float* __restrict__ logits,
                             const float* __restrict__ reg,
                             const float* __restrict__ props) {
    int warp = (blockIdx.x * blockDim.x + threadIdx.x) >> 5;
    int lane = threadIdx.x & 31;
    if (warp >= Bv * Nv) return;

    const float* lrow = logits + (size_t)warp * Cv;
    float l0 = lrow[lane];
    float l1 = lrow[32 + lane];
    float l2 = (64 + lane < Cv) ? lrow[64 + lane] : -3.402823466e38f;
    float m = fmaxf(l0, fmaxf(l1, l2));
    #pragma unroll
    for (int o = 16; o; o >>= 1) m = fmaxf(m, __shfl_xor_sync(0xFFFFFFFFu, m, o));
    float e0 = expf(l0 - m), e1 = expf(l1 - m);
    float e2 = (64 + lane < Cv) ? expf(l2 - m) : 0.0f;
    float s = e0 + e1 + e2;
    #pragma unroll
    for (int o = 16; o; o >>= 1) s += __shfl_xor_sync(0xFFFFFFFFu, s, o);

    int b = warp / Nv, p = warp % Nv;
    const float* pb = props + (size_t)warp * 4;
    float px1 = pb[0], py1 = pb[1], px2 = pb[2], py2 = pb[3];

    float* outsc = g_scores + (size_t)b * NIMG + (size_t)p * FG;
    const float* rrow = reg + (size_t)warp * REGW;

    float ev[3] = {e0, e1, e2};
    #pragma unroll
    for (int k = 0; k < 3; k++) {
        int c = lane + 32 * k;
        if (c >= 1 && c <= FG) {
            float sc = ev[k] / s;
            float4 r = *reinterpret_cast<const float4*>(rrow + c * 4);
            Box bx = decode_one(r, px1, py1, px2, py2);
            float ws = bx.x2 - bx.x1, hs = bx.y2 - bx.y1;
            bool valid = (sc > 0.05f) && (ws >= 0.01f) && (hs >= 0.01f);
            float msc = valid ? sc : -1.0f;
            outsc[c - 1] = msc;
            if (valid)
                atomicAdd(&g_hist[b * NBINS + (orderf(msc) >> 16)], 1u);
        }
    }
}

// =====================================================================
// K2a: per image, find threshold bin. Warp-per-chunk coalesced sums,
// then selected chunk staged to smem before serial scan.
// =====================================================================
__global__ void __launch_bounds__(1024, 1) findthr_kernel() {
    int b = blockIdx.x, tid = threadIdx.x;
    int warp = tid >> 5, lane = tid & 31;
    __shared__ unsigned csum[256];
    __shared__ unsigned bins[256];
    __shared__ int sel_c;
    __shared__ unsigned sel_acc;
    const unsigned* h = g_hist + b * NBINS;

    for (int c = warp; c < 256; c += 32) {
        unsigned s = 0;
        for (int j = lane; j < 256; j += 32) s += h[c * 256 + j];
        #pragma unroll
        for (int o = 16; o; o >>= 1) s += __shfl_xor_sync(0xFFFFFFFFu, s, o);
        if (lane == 0) csum[c] = s;
    }
    __syncthreads();
    if (tid == 0) {
        unsigned acc = 0;
        int c = 255;
        for (; c >= 0; c--) {
            if (acc + csum[c] >= TOPK) break;
            acc += csum[c];
        }
        sel_c = c; sel_acc = acc;
    }
    __syncthreads();
    int c = sel_c;
    if (c >= 0)
        for (int j = tid; j < 256; j += 1024) bins[j] = h[c * 256 + j];
    __syncthreads();
    if (tid == 0) {
        unsigned thr = 0;
        if (c >= 0) {
            unsigned acc = sel_acc;
            int bin = 255;
            for (; bin >= 0; bin--) {
                acc += bins[bin];
                if (acc >= TOPK) break;
            }
            thr = (unsigned)(c * 256 + (bin >= 0 ? bin : 0));
        }
        g_thr[b] = thr;
    }
}

// =====================================================================
// K2b: gather composite keys with bin >= thr (float4-vectorized).
// =====================================================================
__global__ void gather_kernel() {
    int b   = blockIdx.x >> 5;
    int bi  = blockIdx.x & 31;
    int tid = threadIdx.x;
    const float4* sc4 = reinterpret_cast<const float4*>(g_scores + (size_t)b * NIMG);
    unsigned thr = g_thr[b];
    for (int i4 = bi * 256 + tid; i4 < NIMG / 4; i4 += 32 * 256) {
        float4 v = sc4[i4];
        float vs[4] = {v.x, v.y, v.z, v.w};
        #pragma unroll
        for (int c = 0; c < 4; c++) {
            unsigned u = orderf(vs[c]);
            if ((u >> 16) >= thr) {
                unsigned i = (unsigned)(i4 * 4 + c);
                unsigned pos = atomicAdd(&g_gcnt[b], 1u);
                if (pos < GCAP)
                    g_cand[(size_t)b * GCAP + pos] =
                        ((u64)u << 32) | (u64)(0xFFFFFFFFu - i);
            }
        }
    }
}

// =====================================================================
// K2c+K3a fused: per-image bitonic sort (desc) of gathered keys, then
// decode/prep the top-2048 in the same block (no g_keys roundtrip).
// =====================================================================
__global__ void __launch_bounds__(1024, 1) sortprep_kernel(const float* __restrict__ reg,
                                                           const float* __restrict__ props) {
    extern __shared__ u64 skeys[];            // [GCAP]
    __shared__ float4 sbox[TOPK];             // 32KB static
    __shared__ float  sred[33];
    __shared__ u64    svalid[NWORDS];

    int b = blockIdx.x, tid = threadIdx.x;
    unsigned cnt = g_gcnt[b];
    if (cnt > GCAP) cnt = GCAP;
    unsigned P2 = 2048;
    while (P2 < cnt) P2 <<= 1;
    for (unsigned i = tid; i < P2; i += 1024)
        skeys[i] = (i < cnt) ? g_cand[(size_t)b * GCAP + i] : 0ull;
    if (tid < NWORDS) svalid[tid] = 0ull;
    __syncthreads();
    for (unsigned kk = 2; kk <= P2; kk <<= 1) {
        for (unsigned j = kk >> 1; j; j >>= 1) {
            for (unsigned i = tid; i < P2; i += 1024) {
                unsigned p = i ^ j;
                if (p > i) {
                    bool desc = ((i & kk) == 0);
                    u64 a = skeys[i], c = skeys[p];
                    if (desc ? (a < c) : (a > c)) { skeys[i] = c; skeys[p] = a; }
                }
            }
            __syncthreads();
        }
    }

    // ---- prep: decode the sorted top-2048, block max, stage to gmem ----
    float lmax = -3.402823466e38f;
    for (int r = tid; r < TOPK; r += 1024) {
        u64 key = skeys[r];
        unsigned idx = 0xFFFFFFFFu - (unsigned)(key & 0xFFFFFFFFull);
        if (idx >= NIMG) idx = NIMG - 1;     // safety clamp (padding)
        float score  = unorderf((unsigned)(key >> 32));
        int p = idx / FG, cls = (int)(idx % FG) + 1;
        const float* pb = props + ((size_t)b * Nv + p) * 4;
        float4 rr = *reinterpret_cast<const float4*>(reg + ((size_t)b * Nv + p) * REGW + cls * 4);
        Box bx = decode_one(rr, pb[0], pb[1], pb[2], pb[3]);
        sbox[r] = make_float4(bx.x1, bx.y1, bx.x2, bx.y2);
        g_cscore[(size_t)b * TOPK + r] = score;
        g_clabel[(size_t)b * TOPK + r] = cls;
        if (score > 0.0f)
            atomicOr(&svalid[r >> 6], 1ull << (r & 63));
        lmax = fmaxf(lmax, fmaxf(fmaxf(bx.x1, bx.y1), fmaxf(bx.x2, bx.y2)));
    }
    #pragma unroll
    for (int o = 16; o; o >>= 1) lmax = fmaxf(lmax, __shfl_xor_sync(0xFFFFFFFFu, lmax, o));
    if ((tid & 31) == 0) sred[tid >> 5] = lmax;
    __syncthreads();
    if (tid < 32) {
        float v = sred[tid];
        #pragma unroll
        for (int o = 16; o; o >>= 1) v = fmaxf(v, __shfl_xor_sync(0xFFFFFFFFu, v, o));
        if (tid == 0) sred[32] = v;
    }
    __syncthreads();
    float step = sred[32] + 1.0f;

    for (int r = tid; r < TOPK; r += 1024) {
        u64 key = skeys[r];
        unsigned idx = 0xFFFFFFFFu - (unsigned)(key & 0xFFFFFFFFull);
        if (idx >= NIMG) idx = NIMG - 1;
        int cls = (int)(idx % FG) + 1;
        float off = (float)cls * step;
        float4 cb = sbox[r];
        g_cbox[(size_t)b * TOPK + r] = cb;
        g_obox[(size_t)b * TOPK + r] = make_float4(cb.x + off, cb.y + off, cb.z + off, cb.w + off);
    }
    if (tid < NWORDS) g_valid[b * NWORDS + tid] = svalid[tid];
}

// =====================================================================
// K3b: suppression bitmask. Bv*128 blocks (16-row tiles), 256 thr.
// Division replaced by a band test; exact div only in the ambiguous
// band (bit-exact). Sub-diagonal words never written (zero-init).
// =====================================================================
__global__ void __launch_bounds__(256, 5) mask_kernel() {
    __shared__ float4 ob[TOPK];      // 32KB offset boxes
    __shared__ float  ar[TOPK];      // 8KB areas

    int b    = blockIdx.x >> 7;
    int tile = blockIdx.x & 127;
    int tid  = threadIdx.x;
    int rowbase = tile * 16;
    int wmin = rowbase >> 6;
    int lo   = wmin << 6;

    for (int i = lo + tid; i < TOPK; i += 256) {
        float4 v = g_obox[(size_t)b * TOPK + i];
        ob[i] = v;
        ar[i] = (v.z - v.x) * (v.w - v.y);
    }
    __syncthreads();

    int w = tid & 31;
    if (w < wmin) return;
    int r0 = rowbase + (tid >> 5) * 2;

    float4 rb0 = ob[r0],     rb1 = ob[r0 + 1];
    float  aa0 = ar[r0],     aa1 = ar[r0 + 1];
    u64 acc0 = 0ull, acc1 = 0ull;

    #pragma unroll 4
    for (int jj = 0; jj < 64; jj++) {
        int j = w * 64 + jj;
        float4 bj = ob[j];
        float bar = ar[j];
        {
            float ltx = fmaxf(rb0.x, bj.x), lty = fmaxf(rb0.y, bj.y);
            float rbx = fminf(rb0.z, bj.z), rby = fminf(rb0.w, bj.w);
            float ww  = fmaxf(rbx - ltx, 0.0f), hh = fmaxf(rby - lty, 0.0f);
            float inter = ww * hh;
            float U = (aa0 + bar) - inter;
            float hU = 0.5f * U;
            bool sup;
            if (inter > hU * 1.000001f)       sup = true;
            else if (inter < hU * 0.999999f)  sup = false;
            else                               sup = (inter / U) > 0.5f;
            if (sup && (j > r0)) acc0 |= (1ull << jj);
        }
        {
            float ltx = fmaxf(rb1.x, bj.x), lty = fmaxf(rb1.y, bj.y);
            float rbx = fminf(rb1.z, bj.z), rby = fminf(rb1.w, bj.w);
            float ww  = fmaxf(rbx - ltx, 0.0f), hh = fmaxf(rby - lty, 0.0f);
            float inter = ww * hh;
            float U = (aa1 + bar) - inter;
            float hU = 0.5f * U;
            bool sup;
            if (inter > hU * 1.000001f)       sup = true;
            else if (inter < hU * 0.999999f)  sup = false;
            else                               sup = (inter / U) > 0.5f;
            if (sup && (j > r0 + 1)) acc1 |= (1ull << jj);
        }
    }
    g_mask[((size_t)b * TOPK + r0)     * NWORDS + w] = acc0;
    g_mask[((size_t)b * TOPK + r0 + 1) * NWORDS + w] = acc1;
}

// =====================================================================
// K3c: serial reduce (one warp per image) + emission. 16-row batches:
// the owner lane decides all 16 rows LOCALLY in registers (its cur[k]
// holds the diagonal suppression bits), then ONE shfl broadcasts
// kept16 and all lanes apply statically-unrolled predicated ORs.
// All indexing static -> fully register resident. Bit-exact greedy.
// =====================================================================
__global__ void __launch_bounds__(32, 1) reduce_emit_kernel(float* __restrict__ out) {
    int b    = blockIdx.x;
    int lane = threadIdx.x;
    const u64* mrow = g_mask + (size_t)b * TOPK * NWORDS;

    u64 vw   = g_valid[b * NWORDS + lane];
    u64 supp = 0ull;

    u64 cur[16], nxt[16];
    #pragma unroll
    for (int k = 0; k < 16; k++) cur[k] = mrow[(size_t)k * NWORDS + lane];

    for (int base = 0; base < TOPK; base += 16) {
        int nb = base + 16;
        if (nb < TOPK) {
            #pragma unroll
            for (int k = 0; k < 16; k++) nxt[k] = mrow[(size_t)(nb + k) * NWORDS + lane];
        }
        int owner = base >> 6;
        int bit0  = base & 63;
        unsigned kept16 = 0;
        if (lane == owner) {
            u64 s = supp;
            #pragma unroll
            for (int k = 0; k < 16; k++) {
                int bit = bit0 + k;
                if (((vw >> bit) & 1ull) && !((s >> bit) & 1ull)) {
                    kept16 |= (1u << k);
                    s |= cur[k];
                }
            }
        }
        kept16 = __shfl_sync(0xFFFFFFFFu, kept16, owner);
        u64 t0 = 0ull, t1 = 0ull;
        #pragma unroll
        for (int k = 0; k < 16; k += 2) {
            if (kept16 & (1u << k))       t0 |= cur[k];
            if (kept16 & (1u << (k + 1))) t1 |= cur[k + 1];
        }
        supp |= t0 | t1;
        #pragma unroll
        for (int k = 0; k < 16; k++) cur[k] = nxt[k];
    }

    u64 keep = vw & ~supp;

    // warp exclusive scan of per-word keep counts
    int cnt = __popcll(keep);
    int inc = cnt;
    #pragma unroll
    for (int o = 1; o < 32; o <<= 1) {
        int v = __shfl_up_sync(0xFFFFFFFFu, inc, o);
        if (lane >= o) inc += v;
    }
    int excl  = inc - cnt;
    int total = __shfl_sync(0xFFFFFFFFu, inc, 31);

    float* oboxes  = out;                     // [B,100,4]
    float* oscores = out + Bv * DETS * 4;     // [B,100]
    float* olabels = out + Bv * DETS * 5;     // [B,100]

    for (int k = 0; k < 64; k++) {
        int r = lane * 64 + k;
        u64 below = (k == 0) ? 0ull : (keep & ((1ull << k) - 1ull));
        int kb   = excl + __popcll(below);
        int kp   = (int)((keep >> k) & 1ull);
        int slot = kp ? kb : total + (r - kb);
        if (slot < DETS) {
            float4 cb = g_cbox[(size_t)b * TOPK + r];
            float* obp = oboxes + ((size_t)b * DETS + slot) * 4;
            obp[0] = cb.x; obp[1] = cb.y; obp[2] = cb.z; obp[3] = cb.w;
            oscores[b * DETS + slot] = kp ? g_cscore[(size_t)b * TOPK + r] : -1.0f;
            olabels[b * DETS + slot] = (float)g_clabel[(size_t)b * TOPK + r];
        }
    }
}

extern "C" void kernel_launch(void* const* d_in, const int* in_sizes, int n_in,
                              void* d_out, int out_size) {
    const float* logits = (const float*)d_in[0];   // [16000, 91]
    const float* reg    = (const float*)d_in[1];   // [16000, 364]
    const float* props  = (const float*)d_in[2];   // [8, 2000, 4]
    float* out = (float*)d_out;

    zero_kernel<<<(Bv * NBINS + 1023) / 1024, 1024>>>();
    score_kernel<<<(Bv * Nv + 7) / 8, 256>>>(logits, reg, props);
    findthr_kernel<<<Bv, 1024>>>();
    gather_kernel<<<Bv * 32, 256>>>();
    cudaFuncSetAttribute(sortprep_kernel, cudaFuncAttributeMaxDynamicSharedMemorySize,
                         GCAP * (int)sizeof(u64));
    sortprep_kernel<<<Bv, 1024, GCAP * sizeof(u64)>>>(reg, props);
    mask_kernel<<<Bv * 128, 256>>>();
    reduce_emit_kernel<<<Bv, 32>>>(out);
}

// round 8
// speedup vs baseline: 2.1684x; 1.2450x over previous
#include <cuda_runtime.h>
#include <math.h>

#define Bv   8
#define Nv   2000
#define Cv   91
#define FG   90
#define NIMG (Nv*FG)      /* 180000 candidates per image */
#define TOPK 2048
#define DETS 100
#define REGW (Cv*4)       /* 364 floats per proposal row */
#define NWORDS 32         /* 2048/64 */
#define NBINS 4096        /* restricted: ordered top-16 bits - 0xB000 */
#define HBASE 0xB000u
#define GCAP  16384

typedef unsigned long long u64;

__device__ float g_scores[Bv*NIMG];             // masked scores (valid ? score : -1)
__device__ unsigned g_hist[Bv*NBINS];
__device__ unsigned g_gcnt[Bv];
__device__ u64 g_cand[Bv*GCAP];
__device__ float4 g_cbox[Bv*TOPK];              // clipped boxes
__device__ float4 g_obox[Bv*TOPK];              // offset boxes
__device__ float  g_cscore[Bv*TOPK];
__device__ int    g_clabel[Bv*TOPK];
__device__ u64 g_valid[Bv*NWORDS];
__device__ u64 g_mask[Bv*TOPK*NWORDS];          // 4 MB suppression matrix

// ---------- order-preserving float<->uint ----------
__device__ __forceinline__ unsigned orderf(float f) {
    unsigned u = __float_as_uint(f);
    return (u & 0x80000000u) ? ~u : (u | 0x80000000u);
}
__device__ __forceinline__ float unorderf(unsigned u) {
    u = (u & 0x80000000u) ? (u ^ 0x80000000u) : ~u;
    return __uint_as_float(u);
}

struct Box { float x1, y1, x2, y2; };

// Replicates the JAX decode + clip exactly (fp32 op sequence).
__device__ __forceinline__ Box decode_one(float4 r, float x1, float y1, float x2, float y2) {
    const float CLIPV = 4.135166556742356f;   // log(1000/16) as f32
    float w  = x2 - x1, h = y2 - y1;
    float cx = x1 + 0.5f * w, cy = y1 + 0.5f * h;
    float dx = r.x / 10.0f, dy = r.y / 10.0f;
    float dw = fminf(r.z / 5.0f, CLIPV);
    float dh = fminf(r.w / 5.0f, CLIPV);
    float pcx = dx * w + cx, pcy = dy * h + cy;
    float pw  = expf(dw) * w, ph = expf(dh) * h;
    Box o;
    o.x1 = pcx - 0.5f * pw; o.y1 = pcy - 0.5f * ph;
    o.x2 = pcx + 0.5f * pw; o.y2 = pcy + 0.5f * ph;
    o.x1 = fminf(fmaxf(o.x1, 0.0f), 1333.0f);
    o.y1 = fminf(fmaxf(o.y1, 0.0f),  800.0f);
    o.x2 = fminf(fmaxf(o.x2, 0.0f), 1333.0f);
    o.y2 = fminf(fmaxf(o.y2, 0.0f),  800.0f);
    return o;
}

// =====================================================================
// K0: zero histogram + gather counters (graph-replay determinism)
// =====================================================================
__global__ void zero_kernel() {
    unsigned i = blockIdx.x * 1024u + threadIdx.x;
    if (i < Bv * NBINS) g_hist[i] = 0u;
    if (i < Bv) g_gcnt[i] = 0u;
}

// =====================================================================
// K1: one warp per proposal. Softmax over 91 classes, decode fg boxes,
// write masked score, histogram valid scores (restricted 4096 bins).
// =====================================================================
__global__ void score_kernel(const float* __restrict__ logits,
                             const float* __restrict__ reg,
                             const float* __restrict__ props) {
    int warp = (blockIdx.x * blockDim.x + threadIdx.x) >> 5;
    int lane = threadIdx.x & 31;
    if (warp >= Bv * Nv) return;

    const float* lrow = logits + (size_t)warp * Cv;
    float l0 = lrow[lane];
    float l1 = lrow[32 + lane];
    float l2 = (64 + lane < Cv) ? lrow[64 + lane] : -3.402823466e38f;
    float m = fmaxf(l0, fmaxf(l1, l2));
    #pragma unroll
    for (int o = 16; o; o >>= 1) m = fmaxf(m, __shfl_xor_sync(0xFFFFFFFFu, m, o));
    float e0 = expf(l0 - m), e1 = expf(l1 - m);
    float e2 = (64 + lane < Cv) ? expf(l2 - m) : 0.0f;
    float s = e0 + e1 + e2;
    #pragma unroll
    for (int o = 16; o; o >>= 1) s += __shfl_xor_sync(0xFFFFFFFFu, s, o);

    int b = warp / Nv, p = warp % Nv;
    const float* pb = props + (size_t)warp * 4;
    float px1 = pb[0], py1 = pb[1], px2 = pb[2], py2 = pb[3];

    float* outsc = g_scores + (size_t)b * NIMG + (size_t)p * FG;
    const float* rrow = reg + (size_t)warp * REGW;

    float ev[3] = {e0, e1, e2};
    #pragma unroll
    for (int k = 0; k < 3; k++) {
        int c = lane + 32 * k;
        if (c >= 1 && c <= FG) {
            float sc = ev[k] / s;
            float4 r = *reinterpret_cast<const float4*>(rrow + c * 4);
            Box bx = decode_one(r, px1, py1, px2, py2);
            float ws = bx.x2 - bx.x1, hs = bx.y2 - bx.y1;
            bool valid = (sc > 0.05f) && (ws >= 0.01f) && (hs >= 0.01f);
            float msc = valid ? sc : -1.0f;
            outsc[c - 1] = msc;
            if (valid) {
                unsigned bin = (orderf(msc) >> 16) - HBASE;
                if (bin < NBINS)
                    atomicAdd(&g_hist[b * NBINS + bin], 1u);
            }
        }
    }
}

// =====================================================================
// K2: gather. Each block recomputes the threshold bin from the 4096-bin
// histogram (cheap, removes a serialized launch), then gathers composite
// keys (score,~idx) with bin >= thr. float4-vectorized score reads.
// =====================================================================
__global__ void __launch_bounds__(256) gather_kernel() {
    __shared__ unsigned csum[256];
    __shared__ unsigned sthr;
    int b   = blockIdx.x >> 6;
    int bi  = blockIdx.x & 63;
    int tid = threadIdx.x;
    const unsigned* h = g_hist + b * NBINS;

    unsigned ssum = 0;
    int base = tid * 16;
    #pragma unroll
    for (int j = 0; j < 16; j++) ssum += h[base + j];
    csum[tid] = ssum;
    __syncthreads();
    if (tid == 0) {
        unsigned acc = 0;
        int c = 255;
        for (; c >= 0; c--) {
            if (acc + csum[c] >= TOPK) break;
            acc += csum[c];
        }
        unsigned thr = 0;
        if (c >= 0) {
            int bin = c * 16 + 15;
            for (; bin >= c * 16; bin--) {
                acc += h[bin];
                if (acc >= TOPK) break;
            }
            thr = (unsigned)(bin >= c * 16 ? bin : c * 16);
        }
        sthr = thr + HBASE;
    }
    __syncthreads();
    unsigned thr = sthr;

    const float4* sc4 = reinterpret_cast<const float4*>(g_scores + (size_t)b * NIMG);
    for (int i4 = bi * 256 + tid; i4 < NIMG / 4; i4 += 64 * 256) {
        float4 v = sc4[i4];
        float vs[4] = {v.x, v.y, v.z, v.w};
        #pragma unroll
        for (int c = 0; c < 4; c++) {
            unsigned u = orderf(vs[c]);
            if ((u >> 16) >= thr) {
                unsigned i = (unsigned)(i4 * 4 + c);
                unsigned pos = atomicAdd(&g_gcnt[b], 1u);
                if (pos < GCAP)
                    g_cand[(size_t)b * GCAP + pos] =
                        ((u64)u << 32) | (u64)(0xFFFFFFFFu - i);
            }
        }
    }
}

// =====================================================================
// K3: fused select + sort + prep. Radix-select the exact 2048th-largest
// 64-bit key (keys unique), compact the top-2048, bitonic sort 2048,
// then decode/stage boxes, offsets, valid bits.
// =====================================================================
__global__ void __launch_bounds__(1024, 1) sortprep_kernel(const float* __restrict__ reg,
                                                           const float* __restrict__ props) {
    extern __shared__ u64 skeys[];            // [GCAP] staging
    __shared__ u64    sk2[TOPK];              // 16KB compacted+sorted keys
    __shared__ float4 sbox[TOPK];             // 32KB
    __shared__ unsigned hist[256];
    __shared__ float  sred[33];
    __shared__ u64    svalid[NWORDS];
    __shared__ u64    sh_pref;
    __shared__ unsigned sh_k, sh_cpos;

    int b = blockIdx.x, tid = threadIdx.x;
    unsigned cnt = g_gcnt[b];
    if (cnt > GCAP) cnt = GCAP;

    for (unsigned i = tid; i < cnt; i += 1024)
        skeys[i] = g_cand[(size_t)b * GCAP + i];
    if (tid < NWORDS) svalid[tid] = 0ull;
    if (tid == 0) { sh_pref = 0ull; sh_k = TOPK; sh_cpos = 0; }
    __syncthreads();

    if (cnt > TOPK) {
        // ---- radix select: exact 2048th largest key (8x8-bit, top-down) ----
        for (int level = 7; level >= 0; level--) {
            int shift = level * 8;
            for (int i = tid; i < 256; i += 1024) hist[i] = 0;
            __syncthreads();
            u64 pref = sh_pref;
            for (unsigned i = tid; i < cnt; i += 1024) {
                u64 key = skeys[i];
                if (level == 7 || (key >> (shift + 8)) == pref)
                    atomicAdd(&hist[(unsigned)(key >> shift) & 0xFFu], 1u);
            }
            __syncthreads();
            if (tid == 0) {
                unsigned k = sh_k, cum = 0;
                int d = 255;
                for (; d >= 0; d--) {
                    unsigned c = hist[d];
                    if (cum + c >= k) break;
                    cum += c;
                }
                sh_pref = (sh_pref << 8) | (u64)(unsigned)d;
                sh_k = k - cum;
            }
            __syncthreads();
        }
        u64 kstar = sh_pref;
        // ---- compact: keys >= kstar are exactly the top-2048 (unique) ----
        for (unsigned i = tid; i < cnt; i += 1024) {
            u64 key = skeys[i];
            if (key >= kstar) {
                unsigned pos = atomicAdd(&sh_cpos, 1u);
                if (pos < TOPK) sk2[pos] = key;
            }
        }
    } else {
        for (unsigned i = tid; i < TOPK; i += 1024)
            sk2[i] = (i < cnt) ? skeys[i] : 0ull;
    }
    __syncthreads();

    // ---- bitonic sort 2048 descending ----
    for (unsigned kk = 2; kk <= TOPK; kk <<= 1) {
        for (unsigned j = kk >> 1; j; j >>= 1) {
            for (unsigned i = tid; i < TOPK; i += 1024) {
                unsigned p = i ^ j;
                if (p > i) {
                    bool desc = ((i & kk) == 0);
                    u64 a = sk2[i], c = sk2[p];
                    if (desc ? (a < c) : (a > c)) { sk2[i] = c; sk2[p] = a; }
                }
            }
            __syncthreads();
        }
    }

    // ---- prep: decode sorted top-2048, block max, stage to gmem ----
    float lmax = -3.402823466e38f;
    for (int r = tid; r < TOPK; r += 1024) {
        u64 key = sk2[r];
        unsigned idx = 0xFFFFFFFFu - (unsigned)(key & 0xFFFFFFFFull);
        if (idx >= NIMG) idx = NIMG - 1;     // safety clamp (padding)
        float score  = unorderf((unsigned)(key >> 32));
        int p = idx / FG, cls = (int)(idx % FG) + 1;
        const float* pb = props + ((size_t)b * Nv + p) * 4;
        float4 rr = *reinterpret_cast<const float4*>(reg + ((size_t)b * Nv + p) * REGW + cls * 4);
        Box bx = decode_one(rr, pb[0], pb[1], pb[2], pb[3]);
        sbox[r] = make_float4(bx.x1, bx.y1, bx.x2, bx.y2);
        g_cscore[(size_t)b * TOPK + r] = score;
        g_clabel[(size_t)b * TOPK + r] = cls;
        if (score > 0.0f)
            atomicOr(&svalid[r >> 6], 1ull << (r & 63));
        lmax = fmaxf(lmax, fmaxf(fmaxf(bx.x1, bx.y1), fmaxf(bx.x2, bx.y2)));
    }
    #pragma unroll
    for (int o = 16; o; o >>= 1) lmax = fmaxf(lmax, __shfl_xor_sync(0xFFFFFFFFu, lmax, o));
    if ((tid & 31) == 0) sred[tid >> 5] = lmax;
    __syncthreads();
    if (tid < 32) {
        float v = sred[tid];
        #pragma unroll
        for (int o = 16; o; o >>= 1) v = fmaxf(v, __shfl_xor_sync(0xFFFFFFFFu, v, o));
        if (tid == 0) sred[32] = v;
    }
    __syncthreads();
    float step = sred[32] + 1.0f;

    for (int r = tid; r < TOPK; r += 1024) {
        u64 key = sk2[r];
        unsigned idx = 0xFFFFFFFFu - (unsigned)(key & 0xFFFFFFFFull);
        if (idx >= NIMG) idx = NIMG - 1;
        int cls = (int)(idx % FG) + 1;
        float off = (float)cls * step;
        float4 cb = sbox[r];
        g_cbox[(size_t)b * TOPK + r] = cb;
        g_obox[(size_t)b * TOPK + r] = make_float4(cb.x + off, cb.y + off, cb.z + off, cb.w + off);
    }
    if (tid < NWORDS) g_valid[b * NWORDS + tid] = svalid[tid];
}

// =====================================================================
// K4: suppression bitmask. Bv*64 blocks (32-row tiles), 256 thr =
// 32 words x 8 rowgroups x 4 rows. Band test replaces division (exact
// div only in ambiguous band -> bit-exact). Sub-diagonal words never
// written (zero-init).
// =====================================================================
__global__ void __launch_bounds__(256, 5) mask_kernel() {
    __shared__ float4 ob[TOPK];      // 32KB offset boxes
    __shared__ float  ar[TOPK];      // 8KB areas

    int b    = blockIdx.x >> 6;
    int tile = blockIdx.x & 63;
    int tid  = threadIdx.x;
    int rowbase = tile * 32;
    int wmin = rowbase >> 6;
    int lo   = wmin << 6;

    for (int i = lo + tid; i < TOPK; i += 256) {
        float4 v = g_obox[(size_t)b * TOPK + i];
        ob[i] = v;
        ar[i] = (v.z - v.x) * (v.w - v.y);
    }
    __syncthreads();

    int w = tid & 31;
    if (w < wmin) return;
    int r0 = rowbase + (tid >> 5) * 4;

    float4 rb[4]; float aa[4];
    #pragma unroll
    for (int r = 0; r < 4; r++) { rb[r] = ob[r0 + r]; aa[r] = ar[r0 + r]; }
    u64 acc[4] = {0ull, 0ull, 0ull, 0ull};

    #pragma unroll 2
    for (int jj = 0; jj < 64; jj++) {
        int j = w * 64 + jj;
        float4 bj = ob[j];
        float bar = ar[j];
        #pragma unroll
        for (int r = 0; r < 4; r++) {
            float ltx = fmaxf(rb[r].x, bj.x), lty = fmaxf(rb[r].y, bj.y);
            float rbx = fminf(rb[r].z, bj.z), rby = fminf(rb[r].w, bj.w);
            float ww  = fmaxf(rbx - ltx, 0.0f), hh = fmaxf(rby - lty, 0.0f);
            float inter = ww * hh;
            float U = (aa[r] + bar) - inter;
            float hU = 0.5f * U;
            bool sup;
            if (inter > hU * 1.000001f)       sup = true;
            else if (inter < hU * 0.999999f)  sup = false;
            else                               sup = (inter / U) > 0.5f;
            if (sup && (j > r0 + r)) acc[r] |= (1ull << jj);
        }
    }
    #pragma unroll
    for (int r = 0; r < 4; r++)
        g_mask[((size_t)b * TOPK + r0 + r) * NWORDS + w] = acc[r];
}

// =====================================================================
// K5: serial reduce (one warp per image) + emission. 16-row batches:
// owner lane decides all 16 rows locally in registers, one shfl
// broadcast, statically-unrolled predicated ORs. Bit-exact greedy.
// =====================================================================
__global__ void __launch_bounds__(32, 1) reduce_emit_kernel(float* __restrict__ out) {
    int b    = blockIdx.x;
    int lane = threadIdx.x;
    const u64* mrow = g_mask + (size_t)b * TOPK * NWORDS;

    u64 vw   = g_valid[b * NWORDS + lane];
    u64 supp = 0ull;

    u64 cur[16], nxt[16];
    #pragma unroll
    for (int k = 0; k < 16; k++) cur[k] = mrow[(size_t)k * NWORDS + lane];

    for (int base = 0; base < TOPK; base += 16) {
        int nb = base + 16;
        if (nb < TOPK) {
            #pragma unroll
            for (int k = 0; k < 16; k++) nxt[k] = mrow[(size_t)(nb + k) * NWORDS + lane];
        }
        int owner = base >> 6;
        int bit0  = base & 63;
        unsigned kept16 = 0;
        if (lane == owner) {
            u64 s = supp;
            #pragma unroll
            for (int k = 0; k < 16; k++) {
                int bit = bit0 + k;
                if (((vw >> bit) & 1ull) && !((s >> bit) & 1ull)) {
                    kept16 |= (1u << k);
                    s |= cur[k];
                }
            }
        }
        kept16 = __shfl_sync(0xFFFFFFFFu, kept16, owner);
        u64 t0 = 0ull, t1 = 0ull;
        #pragma unroll
        for (int k = 0; k < 16; k += 2) {
            if (kept16 & (1u << k))       t0 |= cur[k];
            if (kept16 & (1u << (k + 1))) t1 |= cur[k + 1];
        }
        supp |= t0 | t1;
        #pragma unroll
        for (int k = 0; k < 16; k++) cur[k] = nxt[k];
    }

    u64 keep = vw & ~supp;

    int cnt = __popcll(keep);
    int inc = cnt;
    #pragma unroll
    for (int o = 1; o < 32; o <<= 1) {
        int v = __shfl_up_sync(0xFFFFFFFFu, inc, o);
        if (lane >= o) inc += v;
    }
    int excl  = inc - cnt;
    int total = __shfl_sync(0xFFFFFFFFu, inc, 31);

    float* oboxes  = out;                     // [B,100,4]
    float* oscores = out + Bv * DETS * 4;     // [B,100]
    float* olabels = out + Bv * DETS * 5;     // [B,100]

    for (int k = 0; k < 64; k++) {
        int r = lane * 64 + k;
        u64 below = (k == 0) ? 0ull : (keep & ((1ull << k) - 1ull));
        int kb   = excl + __popcll(below);
        int kp   = (int)((keep >> k) & 1ull);
        int slot = kp ? kb : total + (r - kb);
        if (slot < DETS) {
            float4 cb = g_cbox[(size_t)b * TOPK + r];
            float* obp = oboxes + ((size_t)b * DETS + slot) * 4;
            obp[0] = cb.x; obp[1] = cb.y; obp[2] = cb.z; obp[3] = cb.w;
            oscores[b * DETS + slot] = kp ? g_cscore[(size_t)b * TOPK + r] : -1.0f;
            olabels[b * DETS + slot] = (float)g_clabel[(size_t)b * TOPK + r];
        }
    }
}

extern "C" void kernel_launch(void* const* d_in, const int* in_sizes, int n_in,
                              void* d_out, int out_size) {
    const float* logits = (const float*)d_in[0];   // [16000, 91]
    const float* reg    = (const float*)d_in[1];   // [16000, 364]
    const float* props  = (const float*)d_in[2];   // [8, 2000, 4]
    float* out = (float*)d_out;

    zero_kernel<<<(Bv * NBINS + 1023) / 1024, 1024>>>();
    score_kernel<<<(Bv * Nv + 7) / 8, 256>>>(logits, reg, props);
    gather_kernel<<<Bv * 64, 256>>>();
    cudaFuncSetAttribute(sortprep_kernel, cudaFuncAttributeMaxDynamicSharedMemorySize,
                         GCAP * (int)sizeof(u64));
    sortprep_kernel<<<Bv, 1024, GCAP * sizeof(u64)>>>(reg, props);
    mask_kernel<<<Bv * 64, 256>>>();
    reduce_emit_kernel<<<Bv, 32>>>(out);
}

// round 11
// speedup vs baseline: 2.3257x; 1.0726x over previous
#include <cuda_runtime.h>
#include <math.h>

#define Bv   8
#define Nv   2000
#define Cv   91
#define FG   90
#define NIMG (Nv*FG)      /* 180000 candidates per image */
#define TOPK 2048
#define DETS 100
#define REGW (Cv*4)       /* 364 floats per proposal row */
#define NWORDS 32         /* 2048/64 */
#define NBINS 4096        /* restricted: ordered top-16 bits - 0xB000 */
#define HBASE 0xB000u
#define GCAP  16384

typedef unsigned long long u64;

__device__ float g_scores[Bv*NIMG];             // masked scores (valid ? score : -1)
__device__ unsigned g_hist[Bv*NBINS];
__device__ float4 g_cbox[Bv*TOPK];              // clipped boxes
__device__ float4 g_obox[Bv*TOPK];              // offset boxes
__device__ float  g_cscore[Bv*TOPK];
__device__ int    g_clabel[Bv*TOPK];
__device__ u64 g_valid[Bv*NWORDS];
__device__ u64 g_mask[Bv*TOPK*NWORDS];          // 4 MB suppression matrix

// ---------- order-preserving float<->uint ----------
__device__ __forceinline__ unsigned orderf(float f) {
    unsigned u = __float_as_uint(f);
    return (u & 0x80000000u) ? ~u : (u | 0x80000000u);
}
__device__ __forceinline__ float unorderf(unsigned u) {
    u = (u & 0x80000000u) ? (u ^ 0x80000000u) : ~u;
    return __uint_as_float(u);
}

struct Box { float x1, y1, x2, y2; };

// Replicates the JAX decode + clip exactly (fp32 op sequence).
__device__ __forceinline__ Box decode_one(float4 r, float x1, float y1, float x2, float y2) {
    const float CLIPV = 4.135166556742356f;   // log(1000/16) as f32
    float w  = x2 - x1, h = y2 - y1;
    float cx = x1 + 0.5f * w, cy = y1 + 0.5f * h;
    float dx = r.x / 10.0f, dy = r.y / 10.0f;
    float dw = fminf(r.z / 5.0f, CLIPV);
    float dh = fminf(r.w / 5.0f, CLIPV);
    float pcx = dx * w + cx, pcy = dy * h + cy;
    float pw  = expf(dw) * w, ph = expf(dh) * h;
    Box o;
    o.x1 = pcx - 0.5f * pw; o.y1 = pcy - 0.5f * ph;
    o.x2 = pcx + 0.5f * pw; o.y2 = pcy + 0.5f * ph;
    o.x1 = fminf(fmaxf(o.x1, 0.0f), 1333.0f);
    o.y1 = fminf(fmaxf(o.y1, 0.0f),  800.0f);
    o.x2 = fminf(fmaxf(o.x2, 0.0f), 1333.0f);
    o.y2 = fminf(fmaxf(o.y2, 0.0f),  800.0f);
    return o;
}

// =====================================================================
// K0: zero histogram (graph-replay determinism)
// =====================================================================
__global__ void zero_kernel() {
    unsigned i = blockIdx.x * 1024u + threadIdx.x;
    if (i < Bv * NBINS) g_hist[i] = 0u;
}

// =====================================================================
// K1: one warp per proposal. Softmax over 91 classes, decode fg boxes,
// write masked score, histogram valid scores (restricted 4096 bins).
// =====================================================================
__global__ void score_kernel(const float* __restrict__ logits,
                             const float* __restrict__ reg,
                             const float* __restrict__ props) {
    int warp = (blockIdx.x * blockDim.x + threadIdx.x) >> 5;
    int lane = threadIdx.x & 31;
    if (warp >= Bv * Nv) return;

    const float* lrow = logits + (size_t)warp * Cv;
    float l0 = lrow[lane];
    float l1 = lrow[32 + lane];
    float l2 = (64 + lane < Cv) ? lrow[64 + lane] : -3.402823466e38f;
    float m = fmaxf(l0, fmaxf(l1, l2));
    #pragma unroll
    for (int o = 16; o; o >>= 1) m = fmaxf(m, __shfl_xor_sync(0xFFFFFFFFu, m, o));
    float e0 = expf(l0 - m), e1 = expf(l1 - m);
    float e2 = (64 + lane < Cv) ? expf(l2 - m) : 0.0f;
    float s = e0 + e1 + e2;
    #pragma unroll
    for (int o = 16; o; o >>= 1) s += __shfl_xor_sync(0xFFFFFFFFu, s, o);

    int b = warp / Nv, p = warp % Nv;
    const float* pb = props + (size_t)warp * 4;
    float px1 = pb[0], py1 = pb[1], px2 = pb[2], py2 = pb[3];

    float* outsc = g_scores + (size_t)b * NIMG + (size_t)p * FG;
    const float* rrow = reg + (size_t)warp * REGW;

    float ev[3] = {e0, e1, e2};
    #pragma unroll
    for (int k = 0; k < 3; k++) {
        int c = lane + 32 * k;
        if (c >= 1 && c <= FG) {
            float sc = ev[k] / s;
            float4 r = *reinterpret_cast<const float4*>(rrow + c * 4);
            Box bx = decode_one(r, px1, py1, px2, py2);
            float ws = bx.x2 - bx.x1, hs = bx.y2 - bx.y1;
            bool valid = (sc > 0.05f) && (ws >= 0.01f) && (hs >= 0.01f);
            float msc = valid ? sc : -1.0f;
            outsc[c - 1] = msc;
            if (valid) {
                unsigned bin = (orderf(msc) >> 16) - HBASE;
                if (bin < NBINS)
                    atomicAdd(&g_hist[b * NBINS + bin], 1u);
            }
        }
    }
}

// =====================================================================
// K2: fused gather + select + sort + prep. One block per image.
//  - threshold bin from histogram (parallel suffix scans)
//  - gather candidates from g_scores directly into smem
//  - exact radix-select 2048th-largest key (parallel digit pick)
//  - compact, bitonic sort 2048, decode + stage for NMS
// =====================================================================
__global__ void __launch_bounds__(1024, 1) sortprep_kernel(const float* __restrict__ reg,
                                                           const float* __restrict__ props) {
    extern __shared__ u64 skeys[];            // [GCAP] staging
    __shared__ u64    sk2[TOPK];              // 16KB compacted+sorted keys
    __shared__ float4 sbox[TOPK];             // 32KB
    __shared__ unsigned hist[256];
    __shared__ unsigned scanA[256], scanB[256];
    __shared__ float  sred[33];
    __shared__ u64    svalid[NWORDS];
    __shared__ u64    sh_pref;
    __shared__ unsigned sh_k, sh_cpos, sh_cnt, sh_thr;

    int b = blockIdx.x, tid = threadIdx.x;
    const unsigned* h = g_hist + b * NBINS;

    if (tid < NWORDS) svalid[tid] = 0ull;
    if (tid == 0) { sh_pref = 0ull; sh_k = TOPK; sh_cpos = 0; sh_cnt = 0; }

    // ---- threshold bin: chunk sums + parallel suffix scan ----
    if (tid < 256) {
        unsigned ssum = 0;
        int base = tid * 16;
        #pragma unroll
        for (int j = 0; j < 16; j++) ssum += h[base + j];
        scanA[tid] = ssum;
    }
    __syncthreads();
    // suffix scan over 256 chunks (Hillis-Steele, ping-pong)
    {
        unsigned* src = scanA; unsigned* dst = scanB;
        for (int off = 1; off < 256; off <<= 1) {
            if (tid < 256)
                dst[tid] = src[tid] + ((tid + off < 256) ? src[tid + off] : 0u);
            __syncthreads();
            unsigned* t = src; src = dst; dst = t;
        }
        // src[c] = sum of chunks >= c  (8 iterations -> src == scanA)
        if (tid < 256) {
            unsigned Sc  = src[tid];
            unsigned Sc1 = (tid < 255) ? src[tid + 1] : 0u;
            if (Sc >= TOPK && Sc1 < TOPK) {
                // chunk found; serial scan of just 16 bins
                unsigned acc = Sc1;
                int bin = tid * 16 + 15;
                for (; bin >= tid * 16; bin--) {
                    acc += h[bin];
                    if (acc >= TOPK) break;
                }
                sh_thr = (unsigned)(bin >= tid * 16 ? bin : tid * 16) + HBASE;
            }
            if (tid == 0 && src[0] < TOPK) sh_thr = HBASE;   // fewer than TOPK valid
        }
    }
    __syncthreads();
    unsigned thr = sh_thr;

    // ---- gather candidates into smem ----
    const float4* sc4 = reinterpret_cast<const float4*>(g_scores + (size_t)b * NIMG);
    for (int i4 = tid; i4 < NIMG / 4; i4 += 1024) {
        float4 v = sc4[i4];
        float vs[4] = {v.x, v.y, v.z, v.w};
        #pragma unroll
        for (int c = 0; c < 4; c++) {
            unsigned u = orderf(vs[c]);
            if ((u >> 16) >= thr) {
                unsigned i = (unsigned)(i4 * 4 + c);
                unsigned pos = atomicAdd(&sh_cnt, 1u);
                if (pos < GCAP)
                    skeys[pos] = ((u64)u << 32) | (u64)(0xFFFFFFFFu - i);
            }
        }
    }
    __syncthreads();
    unsigned cnt = sh_cnt;
    if (cnt > GCAP) cnt = GCAP;

    if (cnt > TOPK) {
        // ---- radix select: exact 2048th largest key (8x8-bit, top-down) ----
        for (int level = 7; level >= 0; level--) {
            int shift = level * 8;
            if (tid < 256) hist[tid] = 0;
            __syncthreads();
            u64 pref = sh_pref;
            unsigned k = sh_k;
            for (unsigned i = tid; i < cnt; i += 1024) {
                u64 key = skeys[i];
                if (level == 7 || (key >> (shift + 8)) == pref)
                    atomicAdd(&hist[(unsigned)(key >> shift) & 0xFFu], 1u);
            }
            __syncthreads();
            // parallel suffix scan of 256 digit counts
            unsigned* src = scanA; unsigned* dst = scanB;
            if (tid < 256) src[tid] = hist[tid];
            __syncthreads();
            for (int off = 1; off < 256; off <<= 1) {
                if (tid < 256)
                    dst[tid] = src[tid] + ((tid + off < 256) ? src[tid + off] : 0u);
                __syncthreads();
                unsigned* t = src; src = dst; dst = t;
            }
            if (tid < 256) {
                unsigned Sd  = src[tid];
                unsigned Sd1 = (tid < 255) ? src[tid + 1] : 0u;
                if (Sd >= k && Sd1 < k) {
                    sh_pref = (pref << 8) | (u64)(unsigned)tid;
                    sh_k = k - Sd1;
                }
            }
            __syncthreads();
        }
        u64 kstar = sh_pref;
        // ---- compact: keys >= kstar are exactly the top-2048 (unique) ----
        for (unsigned i = tid; i < cnt; i += 1024) {
            u64 key = skeys[i];
            if (key >= kstar) {
                unsigned pos = atomicAdd(&sh_cpos, 1u);
                if (pos < TOPK) sk2[pos] = key;
            }
        }
    } else {
        for (unsigned i = tid; i < TOPK; i += 1024)
            sk2[i] = (i < cnt) ? skeys[i] : 0ull;
    }
    __syncthreads();

    // ---- bitonic sort 2048 descending ----
    for (unsigned kk = 2; kk <= TOPK; kk <<= 1) {
        for (unsigned j = kk >> 1; j; j >>= 1) {
            for (unsigned i = tid; i < TOPK; i += 1024) {
                unsigned p = i ^ j;
                if (p > i) {
                    bool desc = ((i & kk) == 0);
                    u64 a = sk2[i], c = sk2[p];
                    if (desc ? (a < c) : (a > c)) { sk2[i] = c; sk2[p] = a; }
                }
            }
            __syncthreads();
        }
    }

    // ---- prep: decode sorted top-2048, block max, stage to gmem ----
    float lmax = -3.402823466e38f;
    for (int r = tid; r < TOPK; r += 1024) {
        u64 key = sk2[r];
        unsigned idx = 0xFFFFFFFFu - (unsigned)(key & 0xFFFFFFFFull);
        if (idx >= NIMG) idx = NIMG - 1;     // safety clamp (padding)
        float score  = unorderf((unsigned)(key >> 32));
        int p = idx / FG, cls = (int)(idx % FG) + 1;
        const float* pb = props + ((size_t)b * Nv + p) * 4;
        float4 rr = *reinterpret_cast<const float4*>(reg + ((size_t)b * Nv + p) * REGW + cls * 4);
        Box bx = decode_one(rr, pb[0], pb[1], pb[2], pb[3]);
        sbox[r] = make_float4(bx.x1, bx.y1, bx.x2, bx.y2);
        g_cscore[(size_t)b * TOPK + r] = score;
        g_clabel[(size_t)b * TOPK + r] = cls;
        if (score > 0.0f)
            atomicOr(&svalid[r >> 6], 1ull << (r & 63));
        lmax = fmaxf(lmax, fmaxf(fmaxf(bx.x1, bx.y1), fmaxf(bx.x2, bx.y2)));
    }
    #pragma unroll
    for (int o = 16; o; o >>= 1) lmax = fmaxf(lmax, __shfl_xor_sync(0xFFFFFFFFu, lmax, o));
    if ((tid & 31) == 0) sred[tid >> 5] = lmax;
    __syncthreads();
    if (tid < 32) {
        float v = sred[tid];
        #pragma unroll
        for (int o = 16; o; o >>= 1) v = fmaxf(v, __shfl_xor_sync(0xFFFFFFFFu, v, o));
        if (tid == 0) sred[32] = v;
    }
    __syncthreads();
    float step = sred[32] + 1.0f;

    for (int r = tid; r < TOPK; r += 1024) {
        u64 key = sk2[r];
        unsigned idx = 0xFFFFFFFFu - (unsigned)(key & 0xFFFFFFFFull);
        if (idx >= NIMG) idx = NIMG - 1;
        int cls = (int)(idx % FG) + 1;
        float off = (float)cls * step;
        float4 cb = sbox[r];
        g_cbox[(size_t)b * TOPK + r] = cb;
        g_obox[(size_t)b * TOPK + r] = make_float4(cb.x + off, cb.y + off, cb.z + off, cb.w + off);
    }
    if (tid < NWORDS) g_valid[b * NWORDS + tid] = svalid[tid];
}

// =====================================================================
// K3: suppression bitmask. Bv*64 blocks (32-row tiles), 256 thr =
// 32 words x 8 rowgroups x 4 rows. Band test replaces division (exact
// div only in ambiguous band -> bit-exact). Sub-diagonal words never
// written (zero-init).
// =====================================================================
__global__ void __launch_bounds__(256, 5) mask_kernel() {
    __shared__ float4 ob[TOPK];      // 32KB offset boxes
    __shared__ float  ar[TOPK];      // 8KB areas

    int b    = blockIdx.x >> 6;
    int tile = blockIdx.x & 63;
    int tid  = threadIdx.x;
    int rowbase = tile * 32;
    int wmin = rowbase >> 6;
    int lo   = wmin << 6;

    for (int i = lo + tid; i < TOPK; i += 256) {
        float4 v = g_obox[(size_t)b * TOPK + i];
        ob[i] = v;
        ar[i] = (v.z - v.x) * (v.w - v.y);
    }
    __syncthreads();

    int w = tid & 31;
    if (w < wmin) return;
    int r0 = rowbase + (tid >> 5) * 4;

    float4 rb[4]; float aa[4];
    #pragma unroll
    for (int r = 0; r < 4; r++) { rb[r] = ob[r0 + r]; aa[r] = ar[r0 + r]; }
    u64 acc[4] = {0ull, 0ull, 0ull, 0ull};

    #pragma unroll 2
    for (int jj = 0; jj < 64; jj++) {
        int j = w * 64 + jj;
        float4 bj = ob[j];
        float bar = ar[j];
        #pragma unroll
        for (int r = 0; r < 4; r++) {
            float ltx = fmaxf(rb[r].x, bj.x), lty = fmaxf(rb[r].y, bj.y);
            float rbx = fminf(rb[r].z, bj.z), rby = fminf(rb[r].w, bj.w);
            float ww  = fmaxf(rbx - ltx, 0.0f), hh = fmaxf(rby - lty, 0.0f);
            float inter = ww * hh;
            float U = (aa[r] + bar) - inter;
            float hU = 0.5f * U;
            bool sup;
            if (inter > hU * 1.000001f)       sup = true;
            else if (inter < hU * 0.999999f)  sup = false;
            else                               sup = (inter / U) > 0.5f;
            if (sup && (j > r0 + r)) acc[r] |= (1ull << jj);
        }
    }
    #pragma unroll
    for (int r = 0; r < 4; r++)
        g_mask[((size_t)b * TOPK + r0 + r) * NWORDS + w] = acc[r];
}

// =====================================================================
// K4: serial reduce (one warp per image) + emission. 16-row batches:
// owner lane decides all 16 rows locally in registers, one shfl
// broadcast, statically-unrolled predicated ORs. Bit-exact greedy.
// =====================================================================
__global__ void __launch_bounds__(32, 1) reduce_emit_kernel(float* __restrict__ out) {
    int b    = blockIdx.x;
    int lane = threadIdx.x;
    const u64* mrow = g_mask + (size_t)b * TOPK * NWORDS;

    u64 vw   = g_valid[b * NWORDS + lane];
    u64 supp = 0ull;

    u64 cur[16], nxt[16];
    #pragma unroll
    for (int k = 0; k < 16; k++) cur[k] = mrow[(size_t)k * NWORDS + lane];

    for (int base = 0; base < TOPK; base += 16) {
        int nb = base + 16;
        if (nb < TOPK) {
            #pragma unroll
            for (int k = 0; k < 16; k++) nxt[k] = mrow[(size_t)(nb + k) * NWORDS + lane];
        }
        int owner = base >> 6;
        int bit0  = base & 63;
        unsigned kept16 = 0;
        if (lane == owner) {
            u64 s = supp;
            #pragma unroll
            for (int k = 0; k < 16; k++) {
                int bit = bit0 + k;
                if (((vw >> bit) & 1ull) && !((s >> bit) & 1ull)) {
                    kept16 |= (1u << k);
                    s |= cur[k];
                }
            }
        }
        kept16 = __shfl_sync(0xFFFFFFFFu, kept16, owner);
        u64 t0 = 0ull, t1 = 0ull;
        #pragma unroll
        for (int k = 0; k < 16; k += 2) {
            if (kept16 & (1u << k))       t0 |= cur[k];
            if (kept16 & (1u << (k + 1))) t1 |= cur[k + 1];
        }
        supp |= t0 | t1;
        #pragma unroll
        for (int k = 0; k < 16; k++) cur[k] = nxt[k];
    }

    u64 keep = vw & ~supp;

    int cnt = __popcll(keep);
    int inc = cnt;
    #pragma unroll
    for (int o = 1; o < 32; o <<= 1) {
        int v = __shfl_up_sync(0xFFFFFFFFu, inc, o);
        if (lane >= o) inc += v;
    }
    int excl  = inc - cnt;
    int total = __shfl_sync(0xFFFFFFFFu, inc, 31);

    float* oboxes  = out;                     // [B,100,4]
    float* oscores = out + Bv * DETS * 4;     // [B,100]
    float* olabels = out + Bv * DETS * 5;     // [B,100]

    for (int k = 0; k < 64; k++) {
        int r = lane * 64 + k;
        u64 below = (k == 0) ? 0ull : (keep & ((1ull << k) - 1ull));
        int kb   = excl + __popcll(below);
        int kp   = (int)((keep >> k) & 1ull);
        int slot = kp ? kb : total + (r - kb);
        if (slot < DETS) {
            float4 cb = g_cbox[(size_t)b * TOPK + r];
            float* obp = oboxes + ((size_t)b * DETS + slot) * 4;
            obp[0] = cb.x; obp[1] = cb.y; obp[2] = cb.z; obp[3] = cb.w;
            oscores[b * DETS + slot] = kp ? g_cscore[(size_t)b * TOPK + r] : -1.0f;
            olabels[b * DETS + slot] = (float)g_clabel[(size_t)b * TOPK + r];
        }
    }
}

extern "C" void kernel_launch(void* const* d_in, const int* in_sizes, int n_in,
                              void* d_out, int out_size) {
    const float* logits = (const float*)d_in[0];   // [16000, 91]
    const float* reg    = (const float*)d_in[1];   // [16000, 364]
    const float* props  = (const float*)d_in[2];   // [8, 2000, 4]
    float* out = (float*)d_out;

    zero_kernel<<<(Bv * NBINS + 1023) / 1024, 1024>>>();
    score_kernel<<<(Bv * Nv + 7) / 8, 256>>>(logits, reg, props);
    cudaFuncSetAttribute(sortprep_kernel, cudaFuncAttributeMaxDynamicSharedMemorySize,
                         GCAP * (int)sizeof(u64));
    sortprep_kernel<<<Bv, 1024, GCAP * sizeof(u64)>>>(reg, props);
    mask_kernel<<<Bv * 64, 256>>>();
    reduce_emit_kernel<<<Bv, 32>>>(out);
}

// round 13
// speedup vs baseline: 2.7424x; 1.1792x over previous
#include <cuda_runtime.h>
#include <math.h>

#define Bv   8
#define Nv   2000
#define Cv   91
#define FG   90
#define NIMG (Nv*FG)      /* 180000 candidates per image */
#define TOPK 2048
#define DETS 100
#define REGW (Cv*4)       /* 364 floats per proposal row */
#define NWORDS 32         /* 2048/64 */
#define NBINS 4096        /* restricted: ordered top-16 bits - 0xB000 */
#define HBASE 0xB000u
#define GCAP  16384

typedef unsigned long long u64;

__device__ float g_scores[Bv*NIMG];             // masked scores (valid ? score : -1)
__device__ unsigned g_hist[Bv*NBINS];
__device__ unsigned g_gcnt[Bv];
__device__ u64 g_cand[Bv*GCAP];
__device__ float4 g_cbox[Bv*TOPK];              // clipped boxes
__device__ float4 g_obox[Bv*TOPK];              // offset boxes
__device__ float  g_cscore[Bv*TOPK];
__device__ int    g_clabel[Bv*TOPK];
__device__ u64 g_valid[Bv*NWORDS];
__device__ u64 g_mask[Bv*TOPK*NWORDS];          // 4 MB suppression matrix

// ---------- order-preserving float<->uint ----------
__device__ __forceinline__ unsigned orderf(float f) {
    unsigned u = __float_as_uint(f);
    return (u & 0x80000000u) ? ~u : (u | 0x80000000u);
}
__device__ __forceinline__ float unorderf(unsigned u) {
    u = (u & 0x80000000u) ? (u ^ 0x80000000u) : ~u;
    return __uint_as_float(u);
}

struct Box { float x1, y1, x2, y2; };

// Replicates the JAX decode + clip exactly (fp32 op sequence).
__device__ __forceinline__ Box decode_one(float4 r, float x1, float y1, float x2, float y2) {
    const float CLIPV = 4.135166556742356f;   // log(1000/16) as f32
    float w  = x2 - x1, h = y2 - y1;
    float cx = x1 + 0.5f * w, cy = y1 + 0.5f * h;
    float dx = r.x / 10.0f, dy = r.y / 10.0f;
    float dw = fminf(r.z / 5.0f, CLIPV);
    float dh = fminf(r.w / 5.0f, CLIPV);
    float pcx = dx * w + cx, pcy = dy * h + cy;
    float pw  = expf(dw) * w, ph = expf(dh) * h;
    Box o;
    o.x1 = pcx - 0.5f * pw; o.y1 = pcy - 0.5f * ph;
    o.x2 = pcx + 0.5f * pw; o.y2 = pcy + 0.5f * ph;
    o.x1 = fminf(fmaxf(o.x1, 0.0f), 1333.0f);
    o.y1 = fminf(fmaxf(o.y1, 0.0f),  800.0f);
    o.x2 = fminf(fmaxf(o.x2, 0.0f), 1333.0f);
    o.y2 = fminf(fmaxf(o.y2, 0.0f),  800.0f);
    return o;
}

// =====================================================================
// K1: one warp per proposal. Softmax over 91 classes, decode fg boxes,
// write masked score, histogram valid scores (restricted 4096 bins).
// (g_hist is zeroed by mask_kernel at the end of the previous call;
//  static zero-init covers the first call.)
// =====================================================================
__global__ void score_kernel(const float* __restrict__ logits,
                             const float* __restrict__ reg,
                             const float* __restrict__ props) {
    int warp = (blockIdx.x * blockDim.x + threadIdx.x) >> 5;
    int lane = threadIdx.x & 31;
    if (warp >= Bv * Nv) return;

    const float* lrow = logits + (size_t)warp * Cv;
    float l0 = lrow[lane];
    float l1 = lrow[32 + lane];
    float l2 = (64 + lane < Cv) ? lrow[64 + lane] : -3.402823466e38f;
    float m = fmaxf(l0, fmaxf(l1, l2));
    #pragma unroll
    for (int o = 16; o; o >>= 1) m = fmaxf(m, __shfl_xor_sync(0xFFFFFFFFu, m, o));
    float e0 = expf(l0 - m), e1 = expf(l1 - m);
    float e2 = (64 + lane < Cv) ? expf(l2 - m) : 0.0f;
    float s = e0 + e1 + e2;
    #pragma unroll
    for (int o = 16; o; o >>= 1) s += __shfl_xor_sync(0xFFFFFFFFu, s, o);

    int b = warp / Nv, p = warp % Nv;
    const float* pb = props + (size_t)warp * 4;
    float px1 = pb[0], py1 = pb[1], px2 = pb[2], py2 = pb[3];

    float* outsc = g_scores + (size_t)b * NIMG + (size_t)p * FG;
    const float* rrow = reg + (size_t)warp * REGW;

    float ev[3] = {e0, e1, e2};
    #pragma unroll
    for (int k = 0; k < 3; k++) {
        int c = lane + 32 * k;
        if (c >= 1 && c <= FG) {
            float sc = ev[k] / s;
            float4 r = *reinterpret_cast<const float4*>(rrow + c * 4);
            Box bx = decode_one(r, px1, py1, px2, py2);
            float ws = bx.x2 - bx.x1, hs = bx.y2 - bx.y1;
            bool valid = (sc > 0.05f) && (ws >= 0.01f) && (hs >= 0.01f);
            float msc = valid ? sc : -1.0f;
            outsc[c - 1] = msc;
            if (valid) {
                unsigned bin = (orderf(msc) >> 16) - HBASE;
                if (bin < NBINS)
                    atomicAdd(&g_hist[b * NBINS + bin], 1u);
            }
        }
    }
}

// =====================================================================
// K2: gather (wide grid). Each block recomputes the threshold with a
// parallel suffix scan, then gathers composite keys (score,~idx) with
// bin >= thr using warp-aggregated atomics. Warp-uniform loop (ballot).
// =====================================================================
__global__ void __launch_bounds__(256) gather_kernel() {
    __shared__ unsigned scanA[256], scanB[256];
    __shared__ unsigned sthr;
    int b   = blockIdx.x >> 7;
    int bi  = blockIdx.x & 127;
    int tid = threadIdx.x;
    int lane = tid & 31;
    const unsigned* h = g_hist + b * NBINS;

    // chunk sums (16 bins per thread) + parallel suffix scan (8 steps)
    {
        unsigned ssum = 0;
        int base = tid * 16;
        #pragma unroll
        for (int j = 0; j < 16; j++) ssum += h[base + j];
        scanA[tid] = ssum;
    }
    __syncthreads();
    unsigned* src = scanA; unsigned* dst = scanB;
    for (int off = 1; off < 256; off <<= 1) {
        dst[tid] = src[tid] + ((tid + off < 256) ? src[tid + off] : 0u);
        __syncthreads();
        unsigned* t = src; src = dst; dst = t;
    }
    {
        unsigned Sc  = src[tid];
        unsigned Sc1 = (tid < 255) ? src[tid + 1] : 0u;
        if (Sc >= TOPK && Sc1 < TOPK) {
            unsigned acc = Sc1;
            int bin = tid * 16 + 15;
            for (; bin >= tid * 16; bin--) {
                acc += h[bin];
                if (acc >= TOPK) break;
            }
            sthr = (unsigned)(bin >= tid * 16 ? bin : tid * 16) + HBASE;
        }
        if (tid == 0 && src[0] < TOPK) sthr = HBASE;
    }
    __syncthreads();
    unsigned thr = sthr;

    const float4* sc4 = reinterpret_cast<const float4*>(g_scores + (size_t)b * NIMG);
    for (int base4 = bi * 256; base4 < NIMG / 4; base4 += 128 * 256) {
        int i4 = base4 + tid;
        bool inb = (i4 < NIMG / 4);
        float4 v = inb ? sc4[i4] : make_float4(-1.f, -1.f, -1.f, -1.f);
        float vs[4] = {v.x, v.y, v.z, v.w};
        #pragma unroll
        for (int c = 0; c < 4; c++) {
            unsigned u = orderf(vs[c]);
            bool hit = inb && ((u >> 16) >= thr);
            unsigned mk = __ballot_sync(0xFFFFFFFFu, hit);
            if (mk) {
                int leader = __ffs(mk) - 1;
                unsigned basep = 0;
                if (lane == leader) basep = atomicAdd(&g_gcnt[b], (unsigned)__popc(mk));
                basep = __shfl_sync(0xFFFFFFFFu, basep, leader);
                if (hit) {
                    unsigned pos = basep + __popc(mk & ((1u << lane) - 1u));
                    unsigned i = (unsigned)(i4 * 4 + c);
                    if (pos < GCAP)
                        g_cand[(size_t)b * GCAP + pos] =
                            ((u64)u << 32) | (u64)(0xFFFFFFFFu - i);
                }
            }
        }
    }
}

// =====================================================================
// K3: select + sort + prep. One block per image. Exact radix-select
// 2048th-largest key (parallel digit pick), compact, bitonic sort 2048,
// decode + stage for NMS.
// =====================================================================
__global__ void __launch_bounds__(1024, 1) sortprep_kernel(const float* __restrict__ reg,
                                                           const float* __restrict__ props) {
    extern __shared__ u64 skeys[];            // [GCAP] staging
    __shared__ u64    sk2[TOPK];              // 16KB compacted+sorted keys
    __shared__ float4 sbox[TOPK];             // 32KB
    __shared__ unsigned hist[256];
    __shared__ unsigned scanA[256], scanB[256];
    __shared__ float  sred[33];
    __shared__ u64    svalid[NWORDS];
    __shared__ u64    sh_pref;
    __shared__ unsigned sh_k, sh_cpos;

    int b = blockIdx.x, tid = threadIdx.x;
    unsigned cnt = g_gcnt[b];
    if (cnt > GCAP) cnt = GCAP;

    for (unsigned i = tid; i < cnt; i += 1024)
        skeys[i] = g_cand[(size_t)b * GCAP + i];
    if (tid < NWORDS) svalid[tid] = 0ull;
    if (tid == 0) { sh_pref = 0ull; sh_k = TOPK; sh_cpos = 0; }
    __syncthreads();

    if (cnt > TOPK) {
        // ---- radix select: exact 2048th largest key (8x8-bit, top-down) ----
        for (int level = 7; level >= 0; level--) {
            int shift = level * 8;
            if (tid < 256) hist[tid] = 0;
            __syncthreads();
            u64 pref = sh_pref;
            unsigned k = sh_k;
            for (unsigned i = tid; i < cnt; i += 1024) {
                u64 key = skeys[i];
                if (level == 7 || (key >> (shift + 8)) == pref)
                    atomicAdd(&hist[(unsigned)(key >> shift) & 0xFFu], 1u);
            }
            __syncthreads();
            unsigned* src = scanA; unsigned* dst = scanB;
            if (tid < 256) src[tid] = hist[tid];
            __syncthreads();
            for (int off = 1; off < 256; off <<= 1) {
                if (tid < 256)
                    dst[tid] = src[tid] + ((tid + off < 256) ? src[tid + off] : 0u);
                __syncthreads();
                unsigned* t = src; src = dst; dst = t;
            }
            if (tid < 256) {
                unsigned Sd  = src[tid];
                unsigned Sd1 = (tid < 255) ? src[tid + 1] : 0u;
                if (Sd >= k && Sd1 < k) {
                    sh_pref = (pref << 8) | (u64)(unsigned)tid;
                    sh_k = k - Sd1;
                }
            }
            __syncthreads();
        }
        u64 kstar = sh_pref;
        // ---- compact: keys >= kstar are exactly the top-2048 (unique) ----
        for (unsigned i = tid; i < cnt; i += 1024) {
            u64 key = skeys[i];
            if (key >= kstar) {
                unsigned pos = atomicAdd(&sh_cpos, 1u);
                if (pos < TOPK) sk2[pos] = key;
            }
        }
    } else {
        for (unsigned i = tid; i < TOPK; i += 1024)
            sk2[i] = (i < cnt) ? skeys[i] : 0ull;
    }
    __syncthreads();

    // ---- bitonic sort 2048 descending ----
    for (unsigned kk = 2; kk <= TOPK; kk <<= 1) {
        for (unsigned j = kk >> 1; j; j >>= 1) {
            for (unsigned i = tid; i < TOPK; i += 1024) {
                unsigned p = i ^ j;
                if (p > i) {
                    bool desc = ((i & kk) == 0);
                    u64 a = sk2[i], c = sk2[p];
                    if (desc ? (a < c) : (a > c)) { sk2[i] = c; sk2[p] = a; }
                }
            }
            __syncthreads();
        }
    }

    // ---- prep: decode sorted top-2048, block max, stage to gmem ----
    float lmax = -3.402823466e38f;
    for (int r = tid; r < TOPK; r += 1024) {
        u64 key = sk2[r];
        unsigned idx = 0xFFFFFFFFu - (unsigned)(key & 0xFFFFFFFFull);
        if (idx >= NIMG) idx = NIMG - 1;     // safety clamp (padding)
        float score  = unorderf((unsigned)(key >> 32));
        int p = idx / FG, cls = (int)(idx % FG) + 1;
        const float* pb = props + ((size_t)b * Nv + p) * 4;
        float4 rr = *reinterpret_cast<const float4*>(reg + ((size_t)b * Nv + p) * REGW + cls * 4);
        Box bx = decode_one(rr, pb[0], pb[1], pb[2], pb[3]);
        sbox[r] = make_float4(bx.x1, bx.y1, bx.x2, bx.y2);
        g_cscore[(size_t)b * TOPK + r] = score;
        g_clabel[(size_t)b * TOPK + r] = cls;
        if (score > 0.0f)
            atomicOr(&svalid[r >> 6], 1ull << (r & 63));
        lmax = fmaxf(lmax, fmaxf(fmaxf(bx.x1, bx.y1), fmaxf(bx.x2, bx.y2)));
    }
    #pragma unroll
    for (int o = 16; o; o >>= 1) lmax = fmaxf(lmax, __shfl_xor_sync(0xFFFFFFFFu, lmax, o));
    if ((tid & 31) == 0) sred[tid >> 5] = lmax;
    __syncthreads();
    if (tid < 32) {
        float v = sred[tid];
        #pragma unroll
        for (int o = 16; o; o >>= 1) v = fmaxf(v, __shfl_xor_sync(0xFFFFFFFFu, v, o));
        if (tid == 0) sred[32] = v;
    }
    __syncthreads();
    float step = sred[32] + 1.0f;

    for (int r = tid; r < TOPK; r += 1024) {
        u64 key = sk2[r];
        unsigned idx = 0xFFFFFFFFu - (unsigned)(key & 0xFFFFFFFFull);
        if (idx >= NIMG) idx = NIMG - 1;
        int cls = (int)(idx % FG) + 1;
        float off = (float)cls * step;
        float4 cb = sbox[r];
        g_cbox[(size_t)b * TOPK + r] = cb;
        g_obox[(size_t)b * TOPK + r] = make_float4(cb.x + off, cb.y + off, cb.z + off, cb.w + off);
    }
    if (tid < NWORDS) g_valid[b * NWORDS + tid] = svalid[tid];
}

// =====================================================================
// K4: suppression bitmask via BALLOT. 512 blocks (tile-major order for
// wave balance): tile = blockIdx>>3 (32 rows), b = blockIdx&7. 8 warps
// x 4 rows; lane = j within a 32-col tile; one __ballot_sync per
// (row, col-tile) produces the 32-bit mask word directly. Same fp op
// sequence (band test) -> bit-exact. Sub-diagonal words never written.
// Also zeroes g_hist/g_gcnt for the next call (runs after consumers).
// =====================================================================
__global__ void __launch_bounds__(256, 4) mask_kernel() {
    __shared__ float4 ob[TOPK];      // 32KB offset boxes
    __shared__ float  ar[TOPK];      // 8KB areas

    int tile = blockIdx.x >> 3;      // 0..63 (heavy tiles first)
    int b    = blockIdx.x & 7;
    int tid  = threadIdx.x;

    // fold: zero histogram slice + gather counters for the next call
    {
        unsigned gi = blockIdx.x * 64u;
        #pragma unroll
        for (int k = 0; k < 64; k += 256) ;   // (noop guard)
        for (int k = tid; k < 64; k += 256) g_hist[gi + k] = 0u;
        if (blockIdx.x == 0 && tid < Bv) g_gcnt[tid] = 0u;
    }

    int rowbase = tile * 32;
    int t0 = rowbase >> 5;           // first 32-wide col tile on/after diagonal

    for (int i = rowbase + tid; i < TOPK; i += 256) {
        float4 v = g_obox[(size_t)b * TOPK + i];
        ob[i] = v;
        ar[i] = (v.z - v.x) * (v.w - v.y);
    }
    __syncthreads();

    int wid  = tid >> 5;
    int lane = tid & 31;
    int r0   = rowbase + wid * 4;    // 8 warps x 4 rows

    float4 rb[4]; float aa[4];
    #pragma unroll
    for (int r = 0; r < 4; r++) { rb[r] = ob[r0 + r]; aa[r] = ar[r0 + r]; }

    unsigned* mrow32 = reinterpret_cast<unsigned*>(g_mask) + (size_t)b * TOPK * 64;

    for (int t = t0; t < 64; t++) {
        int j = t * 32 + lane;
        float4 bj = ob[j];
        float bar = ar[j];
        #pragma unroll
        for (int r = 0; r < 4; r++) {
            float ltx = fmaxf(rb[r].x, bj.x), lty = fmaxf(rb[r].y, bj.y);
            float rbx = fminf(rb[r].z, bj.z), rby = fminf(rb[r].w, bj.w);
            float ww  = fmaxf(rbx - ltx, 0.0f), hh = fmaxf(rby - lty, 0.0f);
            float inter = ww * hh;
            float U = (aa[r] + bar) - inter;
            float hU = 0.5f * U;
            bool sup;
            if (inter > hU * 1.000001f)       sup = true;
            else if (inter < hU * 0.999999f)  sup = false;
            else                               sup = (inter / U) > 0.5f;
            unsigned word = __ballot_sync(0xFFFFFFFFu, sup && (j > r0 + r));
            if (lane == r) mrow32[(size_t)(r0 + r) * 64 + t] = word;
        }
    }
}

// =====================================================================
// K5: serial reduce (one warp per image) + emission. 16-row batches:
// owner lane decides all 16 rows locally in registers, one shfl
// broadcast, statically-unrolled predicated ORs. Bit-exact greedy.
// =====================================================================
__global__ void __launch_bounds__(32, 1) reduce_emit_kernel(float* __restrict__ out) {
    int b    = blockIdx.x;
    int lane = threadIdx.x;
    const u64* mrow = g_mask + (size_t)b * TOPK * NWORDS;

    u64 vw   = g_valid[b * NWORDS + lane];
    u64 supp = 0ull;

    u64 cur[16], nxt[16];
    #pragma unroll
    for (int k = 0; k < 16; k++) cur[k] = mrow[(size_t)k * NWORDS + lane];

    for (int base = 0; base < TOPK; base += 16) {
        int nb = base + 16;
        if (nb < TOPK) {
            #pragma unroll
            for (int k = 0; k < 16; k++) nxt[k] = mrow[(size_t)(nb + k) * NWORDS + lane];
        }
        int owner = base >> 6;
        int bit0  = base & 63;
        unsigned kept16 = 0;
        if (lane == owner) {
            u64 s = supp;
            #pragma unroll
            for (int k = 0; k < 16; k++) {
                int bit = bit0 + k;
                if (((vw >> bit) & 1ull) && !((s >> bit) & 1ull)) {
                    kept16 |= (1u << k);
                    s |= cur[k];
                }
            }
        }
        kept16 = __shfl_sync(0xFFFFFFFFu, kept16, owner);
        u64 t0 = 0ull, t1 = 0ull;
        #pragma unroll
        for (int k = 0; k < 16; k += 2) {
            if (kept16 & (1u << k))       t0 |= cur[k];
            if (kept16 & (1u << (k + 1))) t1 |= cur[k + 1];
        }
        supp |= t0 | t1;
        #pragma unroll
        for (int k = 0; k < 16; k++) cur[k] = nxt[k];
    }

    u64 keep = vw & ~supp;

    int cnt = __popcll(keep);
    int inc = cnt;
    #pragma unroll
    for (int o = 1; o < 32; o <<= 1) {
        int v = __shfl_up_sync(0xFFFFFFFFu, inc, o);
        if (lane >= o) inc += v;
    }
    int excl  = inc - cnt;
    int total = __shfl_sync(0xFFFFFFFFu, inc, 31);

    float* oboxes  = out;                     // [B,100,4]
    float* oscores = out + Bv * DETS * 4;     // [B,100]
    float* olabels = out + Bv * DETS * 5;     // [B,100]

    for (int k = 0; k < 64; k++) {
        int r = lane * 64 + k;
        u64 below = (k == 0) ? 0ull : (keep & ((1ull << k) - 1ull));
        int kb   = excl + __popcll(below);
        int kp   = (int)((keep >> k) & 1ull);
        int slot = kp ? kb : total + (r - kb);
        if (slot < DETS) {
            float4 cb = g_cbox[(size_t)b * TOPK + r];
            float* obp = oboxes + ((size_t)b * DETS + slot) * 4;
            obp[0] = cb.x; obp[1] = cb.y; obp[2] = cb.z; obp[3] = cb.w;
            oscores[b * DETS + slot] = kp ? g_cscore[(size_t)b * TOPK + r] : -1.0f;
            olabels[b * DETS + slot] = (float)g_clabel[(size_t)b * TOPK + r];
        }
    }
}

extern "C" void kernel_launch(void* const* d_in, const int* in_sizes, int n_in,
                              void* d_out, int out_size) {
    const float* logits = (const float*)d_in[0];   // [16000, 91]
    const float* reg    = (const float*)d_in[1];   // [16000, 364]
    const float* props  = (const float*)d_in[2];   // [8, 2000, 4]
    float* out = (float*)d_out;

    score_kernel<<<(Bv * Nv + 7) / 8, 256>>>(logits, reg, props);
    gather_kernel<<<Bv * 128, 256>>>();
    cudaFuncSetAttribute(sortprep_kernel, cudaFuncAttributeMaxDynamicSharedMemorySize,
                         GCAP * (int)sizeof(u64));
    sortprep_kernel<<<Bv, 1024, GCAP * sizeof(u64)>>>(reg, props);
    mask_kernel<<<Bv * 64, 256>>>();
    reduce_emit_kernel<<<Bv, 32>>>(out);
}

// round 15
// speedup vs baseline: 3.4919x; 1.2733x over previous
#include <cuda_runtime.h>
#include <math.h>

#define Bv   8
#define Nv   2000
#define Cv   91
#define FG   90
#define NIMG (Nv*FG)      /* 180000 candidates per image */
#define TOPK 2048
#define DETS 100
#define REGW (Cv*4)       /* 364 floats per proposal row */
#define NBINS 4096        /* restricted: ordered top-16 bits - 0xB000 */
#define HBASE 0xB000u
#define GCAP  16384

typedef unsigned long long u64;

__device__ float g_scores[Bv*NIMG];             // masked scores (valid ? score : -1)
__device__ unsigned g_hist[Bv*NBINS];
__device__ unsigned g_gcnt[Bv];
__device__ u64 g_cand[Bv*GCAP];

// ---------- order-preserving float<->uint ----------
__device__ __forceinline__ unsigned orderf(float f) {
    unsigned u = __float_as_uint(f);
    return (u & 0x80000000u) ? ~u : (u | 0x80000000u);
}
__device__ __forceinline__ float unorderf(unsigned u) {
    u = (u & 0x80000000u) ? (u ^ 0x80000000u) : ~u;
    return __uint_as_float(u);
}

struct Box { float x1, y1, x2, y2; };

// Replicates the JAX decode + clip exactly (fp32 op sequence).
__device__ __forceinline__ Box decode_one(float4 r, float x1, float y1, float x2, float y2) {
    const float CLIPV = 4.135166556742356f;   // log(1000/16) as f32
    float w  = x2 - x1, h = y2 - y1;
    float cx = x1 + 0.5f * w, cy = y1 + 0.5f * h;
    float dx = r.x / 10.0f, dy = r.y / 10.0f;
    float dw = fminf(r.z / 5.0f, CLIPV);
    float dh = fminf(r.w / 5.0f, CLIPV);
    float pcx = dx * w + cx, pcy = dy * h + cy;
    float pw  = expf(dw) * w, ph = expf(dh) * h;
    Box o;
    o.x1 = pcx - 0.5f * pw; o.y1 = pcy - 0.5f * ph;
    o.x2 = pcx + 0.5f * pw; o.y2 = pcy + 0.5f * ph;
    o.x1 = fminf(fmaxf(o.x1, 0.0f), 1333.0f);
    o.y1 = fminf(fmaxf(o.y1, 0.0f),  800.0f);
    o.x2 = fminf(fmaxf(o.x2, 0.0f), 1333.0f);
    o.y2 = fminf(fmaxf(o.y2, 0.0f),  800.0f);
    return o;
}

// =====================================================================
// K1: one warp per proposal. Softmax over 91 classes, decode fg boxes,
// write masked score, histogram valid scores. (g_hist/g_gcnt zeroed by
// nms_kernel tail on the previous call; static zero-init covers call 1.)
// =====================================================================
__global__ void score_kernel(const float* __restrict__ logits,
                             const float* __restrict__ reg,
                             const float* __restrict__ props) {
    int warp = (blockIdx.x * blockDim.x + threadIdx.x) >> 5;
    int lane = threadIdx.x & 31;
    if (warp >= Bv * Nv) return;

    const float* lrow = logits + (size_t)warp * Cv;
    float l0 = lrow[lane];
    float l1 = lrow[32 + lane];
    float l2 = (64 + lane < Cv) ? lrow[64 + lane] : -3.402823466e38f;
    float m = fmaxf(l0, fmaxf(l1, l2));
    #pragma unroll
    for (int o = 16; o; o >>= 1) m = fmaxf(m, __shfl_xor_sync(0xFFFFFFFFu, m, o));
    float e0 = expf(l0 - m), e1 = expf(l1 - m);
    float e2 = (64 + lane < Cv) ? expf(l2 - m) : 0.0f;
    float s = e0 + e1 + e2;
    #pragma unroll
    for (int o = 16; o; o >>= 1) s += __shfl_xor_sync(0xFFFFFFFFu, s, o);

    int b = warp / Nv, p = warp % Nv;
    const float* pb = props + (size_t)warp * 4;
    float px1 = pb[0], py1 = pb[1], px2 = pb[2], py2 = pb[3];

    float* outsc = g_scores + (size_t)b * NIMG + (size_t)p * FG;
    const float* rrow = reg + (size_t)warp * REGW;

    float ev[3] = {e0, e1, e2};
    #pragma unroll
    for (int k = 0; k < 3; k++) {
        int c = lane + 32 * k;
        if (c >= 1 && c <= FG) {
            float sc = ev[k] / s;
            float4 r = *reinterpret_cast<const float4*>(rrow + c * 4);
            Box bx = decode_one(r, px1, py1, px2, py2);
            float ws = bx.x2 - bx.x1, hs = bx.y2 - bx.y1;
            bool valid = (sc > 0.05f) && (ws >= 0.01f) && (hs >= 0.01f);
            float msc = valid ? sc : -1.0f;
            outsc[c - 1] = msc;
            if (valid) {
                unsigned bin = (orderf(msc) >> 16) - HBASE;
                if (bin < NBINS)
                    atomicAdd(&g_hist[b * NBINS + bin], 1u);
            }
        }
    }
}

// =====================================================================
// K2: gather (wide grid). Each block recomputes the threshold with a
// parallel suffix scan, then gathers composite keys (score,~idx) with
// bin >= thr using warp-aggregated atomics.
// =====================================================================
__global__ void __launch_bounds__(256) gather_kernel() {
    __shared__ unsigned scanA[256], scanB[256];
    __shared__ unsigned sthr;
    int b   = blockIdx.x >> 7;
    int bi  = blockIdx.x & 127;
    int tid = threadIdx.x;
    int lane = tid & 31;
    const unsigned* h = g_hist + b * NBINS;

    {
        unsigned ssum = 0;
        int base = tid * 16;
        #pragma unroll
        for (int j = 0; j < 16; j++) ssum += h[base + j];
        scanA[tid] = ssum;
    }
    __syncthreads();
    unsigned* src = scanA; unsigned* dst = scanB;
    for (int off = 1; off < 256; off <<= 1) {
        dst[tid] = src[tid] + ((tid + off < 256) ? src[tid + off] : 0u);
        __syncthreads();
        unsigned* t = src; src = dst; dst = t;
    }
    {
        unsigned Sc  = src[tid];
        unsigned Sc1 = (tid < 255) ? src[tid + 1] : 0u;
        if (Sc >= TOPK && Sc1 < TOPK) {
            unsigned acc = Sc1;
            int bin = tid * 16 + 15;
            for (; bin >= tid * 16; bin--) {
                acc += h[bin];
                if (acc >= TOPK) break;
            }
            sthr = (unsigned)(bin >= tid * 16 ? bin : tid * 16) + HBASE;
        }
        if (tid == 0 && src[0] < TOPK) sthr = HBASE;
    }
    __syncthreads();
    unsigned thr = sthr;

    const float4* sc4 = reinterpret_cast<const float4*>(g_scores + (size_t)b * NIMG);
    for (int base4 = bi * 256; base4 < NIMG / 4; base4 += 128 * 256) {
        int i4 = base4 + tid;
        bool inb = (i4 < NIMG / 4);
        float4 v = inb ? sc4[i4] : make_float4(-1.f, -1.f, -1.f, -1.f);
        float vs[4] = {v.x, v.y, v.z, v.w};
        #pragma unroll
        for (int c = 0; c < 4; c++) {
            unsigned u = orderf(vs[c]);
            bool hit = inb && ((u >> 16) >= thr);
            unsigned mk = __ballot_sync(0xFFFFFFFFu, hit);
            if (mk) {
                int leader = __ffs(mk) - 1;
                unsigned basep = 0;
                if (lane == leader) basep = atomicAdd(&g_gcnt[b], (unsigned)__popc(mk));
                basep = __shfl_sync(0xFFFFFFFFu, basep, leader);
                if (hit) {
                    unsigned pos = basep + __popc(mk & ((1u << lane) - 1u));
                    unsigned i = (unsigned)(i4 * 4 + c);
                    if (pos < GCAP)
                        g_cand[(size_t)b * GCAP + pos] =
                            ((u64)u << 32) | (u64)(0xFFFFFFFFu - i);
                }
            }
        }
    }
}

// =====================================================================
// K3: fused select + sort + decode + per-class NMS + emit. One block
// per image. Cross-class pairs can never suppress (offset gap >= step -
// max_coord > 0 even under fp rounding => inter == 0 exactly), so
// greedy NMS decomposes into independent per-class greedy NMS, each run
// by one warp with the exact same fp op sequence (band test + exact div
// fallback) as the previously passing dense-mask version => bit-exact.
// =====================================================================
__global__ void __launch_bounds__(1024, 1) nms_kernel(const float* __restrict__ reg,
                                                      const float* __restrict__ props,
                                                      float* __restrict__ out) {
    extern __shared__ char dyn[];             // 128KB dynamic
    // phase A view:
    u64* skeys = reinterpret_cast<u64*>(dyn);                 // [GCAP]
    // phase B+ views (valid after compaction barrier):
    float4* cbox  = reinterpret_cast<float4*>(dyn);           // 32KB clipped boxes
    float4* obox  = reinterpret_cast<float4*>(dyn + 32768);   // 32KB offset boxes
    float*  area  = reinterpret_cast<float*>(dyn + 65536);    // 8KB offset-box areas
    float*  ssc   = reinterpret_cast<float*>(dyn + 73728);    // 8KB scores
    int*    slab  = reinterpret_cast<int*>(dyn + 81920);      // 8KB labels
    unsigned short* clsbuf = reinterpret_cast<unsigned short*>(dyn + 90112); // 4KB

    __shared__ u64 sk2[TOPK];                 // 16KB sorted keys
    __shared__ unsigned hist[256];
    __shared__ unsigned scanA[256], scanB[256];
    __shared__ unsigned cnts[128], sincl[128];
    __shared__ unsigned char sup8[TOPK];
    __shared__ u64 keepw[32];
    __shared__ float sred[33];
    __shared__ u64 sh_pref;
    __shared__ unsigned sh_k, sh_cpos;

    int b = blockIdx.x, tid = threadIdx.x;
    int wid = tid >> 5, lane = tid & 31;
    unsigned cnt = g_gcnt[b];
    if (cnt > GCAP) cnt = GCAP;

    for (unsigned i = tid; i < cnt; i += 1024)
        skeys[i] = g_cand[(size_t)b * GCAP + i];
    if (tid < 32) keepw[tid] = 0ull;
    if (tid < 128) cnts[tid] = 0u;
    for (int r = tid; r < TOPK; r += 1024) sup8[r] = 0;
    if (tid == 0) { sh_pref = 0ull; sh_k = TOPK; sh_cpos = 0; }
    __syncthreads();

    if (cnt > TOPK) {
        // ---- radix select: exact 2048th largest key (8x8-bit, top-down) ----
        for (int level = 7; level >= 0; level--) {
            int shift = level * 8;
            if (tid < 256) hist[tid] = 0;
            __syncthreads();
            u64 pref = sh_pref;
            unsigned k = sh_k;
            for (unsigned i = tid; i < cnt; i += 1024) {
                u64 key = skeys[i];
                if (level == 7 || (key >> (shift + 8)) == pref)
                    atomicAdd(&hist[(unsigned)(key >> shift) & 0xFFu], 1u);
            }
            __syncthreads();
            unsigned* src = scanA; unsigned* dst = scanB;
            if (tid < 256) src[tid] = hist[tid];
            __syncthreads();
            for (int off = 1; off < 256; off <<= 1) {
                if (tid < 256)
                    dst[tid] = src[tid] + ((tid + off < 256) ? src[tid + off] : 0u);
                __syncthreads();
                unsigned* t = src; src = dst; dst = t;
            }
            if (tid < 256) {
                unsigned Sd  = src[tid];
                unsigned Sd1 = (tid < 255) ? src[tid + 1] : 0u;
                if (Sd >= k && Sd1 < k) {
                    sh_pref = (pref << 8) | (u64)(unsigned)tid;
                    sh_k = k - Sd1;
                }
            }
            __syncthreads();
        }
        u64 kstar = sh_pref;
        for (unsigned i = tid; i < cnt; i += 1024) {
            u64 key = skeys[i];
            if (key >= kstar) {
                unsigned pos = atomicAdd(&sh_cpos, 1u);
                if (pos < TOPK) sk2[pos] = key;
            }
        }
    } else {
        for (unsigned i = tid; i < TOPK; i += 1024)
            sk2[i] = (i < cnt) ? skeys[i] : 0ull;
    }
    __syncthreads();      // dyn region reusable from here

    // ---- bitonic sort 2048 descending ----
    for (unsigned kk = 2; kk <= TOPK; kk <<= 1) {
        for (unsigned j = kk >> 1; j; j >>= 1) {
            for (unsigned i = tid; i < TOPK; i += 1024) {
                unsigned p = i ^ j;
                if (p > i) {
                    bool desc = ((i & kk) == 0);
                    u64 a = sk2[i], c = sk2[p];
                    if (desc ? (a < c) : (a > c)) { sk2[i] = c; sk2[p] = a; }
                }
            }
            __syncthreads();
        }
    }

    // ---- decode sorted top-2048 into smem, block max ----
    float lmax = -3.402823466e38f;
    for (int r = tid; r < TOPK; r += 1024) {
        u64 key = sk2[r];
        unsigned idx = 0xFFFFFFFFu - (unsigned)(key & 0xFFFFFFFFull);
        if (idx >= NIMG) idx = NIMG - 1;     // safety clamp (padding)
        float score = unorderf((unsigned)(key >> 32));
        int p = idx / FG, cls = (int)(idx % FG) + 1;
        const float* pb = props + ((size_t)b * Nv + p) * 4;
        float4 rr = *reinterpret_cast<const float4*>(reg + ((size_t)b * Nv + p) * REGW + cls * 4);
        Box bx = decode_one(rr, pb[0], pb[1], pb[2], pb[3]);
        cbox[r] = make_float4(bx.x1, bx.y1, bx.x2, bx.y2);
        ssc[r]  = score;
        slab[r] = cls;
        atomicAdd(&cnts[cls], 1u);
        lmax = fmaxf(lmax, fmaxf(fmaxf(bx.x1, bx.y1), fmaxf(bx.x2, bx.y2)));
    }
    #pragma unroll
    for (int o = 16; o; o >>= 1) lmax = fmaxf(lmax, __shfl_xor_sync(0xFFFFFFFFu, lmax, o));
    if (lane == 0) sred[wid] = lmax;
    __syncthreads();
    if (tid < 32) {
        float v = sred[tid];
        #pragma unroll
        for (int o = 16; o; o >>= 1) v = fmaxf(v, __shfl_xor_sync(0xFFFFFFFFu, v, o));
        if (tid == 0) sred[32] = v;
    }
    __syncthreads();
    float step = sred[32] + 1.0f;

    // ---- offset boxes + areas (exact reference fp sequence) ----
    for (int r = tid; r < TOPK; r += 1024) {
        float off = (float)slab[r] * step;
        float4 cb = cbox[r];
        float4 ob = make_float4(cb.x + off, cb.y + off, cb.z + off, cb.w + off);
        obox[r] = ob;
        area[r] = (ob.z - ob.x) * (ob.w - ob.y);
    }

    // ---- inclusive scan of class counts (128 entries, Hillis-Steele) ----
    __syncthreads();
    {
        unsigned* src = scanA; unsigned* dst = scanB;
        if (tid < 128) src[tid] = cnts[tid];
        __syncthreads();
        for (int off = 1; off < 128; off <<= 1) {
            if (tid < 128)
                dst[tid] = src[tid] + ((tid >= (unsigned)off) ? src[tid - off] : 0u);
            __syncthreads();
            unsigned* t = src; src = dst; dst = t;
        }
        if (tid < 128) sincl[tid] = src[tid];
    }
    __syncthreads();

    // ---- stable class bucketing: warp per class, ballot compaction ----
    #pragma unroll
    for (int cc = 0; cc < 3; cc++) {
        int c = 1 + wid + cc * 32;
        if (c <= FG) {
            unsigned seg = sincl[c - 1];
            unsigned pos = 0;
            for (int base = 0; base < TOPK; base += 32) {
                int r = base + lane;
                bool hit = (slab[r] == c);
                unsigned mk = __ballot_sync(0xFFFFFFFFu, hit);
                if (hit)
                    clsbuf[seg + pos + __popc(mk & ((1u << lane) - 1u))] = (unsigned short)r;
                pos += __popc(mk);
            }
        }
    }
    __syncthreads();

    // ---- per-class greedy NMS (warp per class) ----
    #pragma unroll
    for (int cc = 0; cc < 3; cc++) {
        int c = 1 + wid + cc * 32;
        if (c <= FG) {
            unsigned seg = sincl[c - 1];
            int n = (int)(sincl[c] - sincl[c - 1]);
            for (int k = 0; k < n; k++) {
                int rk = clsbuf[seg + k];
                bool act = (ssc[rk] > 0.0f) && (sup8[rk] == 0);
                if (act) {
                    float4 bi = obox[rk];
                    float  ai = area[rk];
                    for (int mi = k + 1 + lane; mi < n; mi += 32) {
                        int rm = clsbuf[seg + mi];
                        float4 bj = obox[rm];
                        float  aj = area[rm];
                        float ltx = fmaxf(bi.x, bj.x), lty = fmaxf(bi.y, bj.y);
                        float rbx = fminf(bi.z, bj.z), rby = fminf(bi.w, bj.w);
                        float ww  = fmaxf(rbx - ltx, 0.0f), hh = fmaxf(rby - lty, 0.0f);
                        float inter = ww * hh;
                        float U = (ai + aj) - inter;
                        float hU = 0.5f * U;
                        bool sup;
                        if (inter > hU * 1.000001f)       sup = true;
                        else if (inter < hU * 0.999999f)  sup = false;
                        else                               sup = (inter / U) > 0.5f;
                        if (sup) sup8[rm] = 1;
                    }
                }
                __syncwarp();
            }
        }
    }
    __syncthreads();

    // ---- keep bits ----
    for (int r = tid; r < TOPK; r += 1024) {
        if (ssc[r] > 0.0f && sup8[r] == 0)
            atomicOr(&keepw[r >> 6], 1ull << (r & 63));
    }
    __syncthreads();

    // ---- emission (warp 0): kept in rank order, then non-kept fill ----
    if (wid == 0) {
        u64 keep = keepw[lane];
        int kc  = __popcll(keep);
        int inc = kc;
        #pragma unroll
        for (int o = 1; o < 32; o <<= 1) {
            int v = __shfl_up_sync(0xFFFFFFFFu, inc, o);
            if (lane >= o) inc += v;
        }
        int excl  = inc - kc;
        int total = __shfl_sync(0xFFFFFFFFu, inc, 31);

        float* oboxes  = out;                     // [B,100,4]
        float* oscores = out + Bv * DETS * 4;     // [B,100]
        float* olabels = out + Bv * DETS * 5;     // [B,100]

        for (int k = 0; k < 64; k++) {
            int r = lane * 64 + k;
            u64 below = (k == 0) ? 0ull : (keep & ((1ull << k) - 1ull));
            int kb   = excl + __popcll(below);
            int kp   = (int)((keep >> k) & 1ull);
            int slot = kp ? kb : total + (r - kb);
            if (slot < DETS) {
                float4 cb = cbox[r];
                float* obp = oboxes + ((size_t)b * DETS + slot) * 4;
                obp[0] = cb.x; obp[1] = cb.y; obp[2] = cb.z; obp[3] = cb.w;
                oscores[b * DETS + slot] = kp ? ssc[r] : -1.0f;
                olabels[b * DETS + slot] = (float)slab[r];
            }
        }
    }

    // ---- zero hist/gcnt for next call ----
    for (int i = tid; i < NBINS; i += 1024) g_hist[b * NBINS + i] = 0u;
    if (tid == 0) g_gcnt[b] = 0u;
}

extern "C" void kernel_launch(void* const* d_in, const int* in_sizes, int n_in,
                              void* d_out, int out_size) {
    const float* logits = (const float*)d_in[0];   // [16000, 91]
    const float* reg    = (const float*)d_in[1];   // [16000, 364]
    const float* props  = (const float*)d_in[2];   // [8, 2000, 4]
    float* out = (float*)d_out;

    score_kernel<<<(Bv * Nv + 7) / 8, 256>>>(logits, reg, props);
    gather_kernel<<<Bv * 128, 256>>>();
    cudaFuncSetAttribute(nms_kernel, cudaFuncAttributeMaxDynamicSharedMemorySize,
                         GCAP * (int)sizeof(u64));
    nms_kernel<<<Bv, 1024, GCAP * sizeof(u64)>>>(reg, props, out);
}

// round 16
// speedup vs baseline: 3.5316x; 1.0114x over previous
#include <cuda_runtime.h>
#include <math.h>

#define Bv   8
#define Nv   2000
#define Cv   91
#define FG   90
#define NIMG (Nv*FG)      /* 180000 candidates per image */
#define TOPK 2048
#define DETS 100
#define REGW (Cv*4)       /* 364 floats per proposal row */
#define NBINS 4096        /* restricted: ordered top-16 bits - 0xB000 */
#define HBASE 0xB000u
#define GCAP  16384

typedef unsigned long long u64;

__device__ float g_scores[Bv*NIMG];             // masked scores (valid ? score : -1)
__device__ unsigned g_hist[Bv*NBINS];
__device__ unsigned g_gcnt[Bv];
__device__ u64 g_cand[Bv*GCAP];

// ---------- order-preserving float<->uint ----------
__device__ __forceinline__ unsigned orderf(float f) {
    unsigned u = __float_as_uint(f);
    return (u & 0x80000000u) ? ~u : (u | 0x80000000u);
}
__device__ __forceinline__ float unorderf(unsigned u) {
    u = (u & 0x80000000u) ? (u ^ 0x80000000u) : ~u;
    return __uint_as_float(u);
}

struct Box { float x1, y1, x2, y2; };

// Replicates the JAX decode + clip exactly (fp32 op sequence).
__device__ __forceinline__ Box decode_one(float4 r, float x1, float y1, float x2, float y2) {
    const float CLIPV = 4.135166556742356f;   // log(1000/16) as f32
    float w  = x2 - x1, h = y2 - y1;
    float cx = x1 + 0.5f * w, cy = y1 + 0.5f * h;
    float dx = r.x / 10.0f, dy = r.y / 10.0f;
    float dw = fminf(r.z / 5.0f, CLIPV);
    float dh = fminf(r.w / 5.0f, CLIPV);
    float pcx = dx * w + cx, pcy = dy * h + cy;
    float pw  = expf(dw) * w, ph = expf(dh) * h;
    Box o;
    o.x1 = pcx - 0.5f * pw; o.y1 = pcy - 0.5f * ph;
    o.x2 = pcx + 0.5f * pw; o.y2 = pcy + 0.5f * ph;
    o.x1 = fminf(fmaxf(o.x1, 0.0f), 1333.0f);
    o.y1 = fminf(fmaxf(o.y1, 0.0f),  800.0f);
    o.x2 = fminf(fmaxf(o.x2, 0.0f), 1333.0f);
    o.y2 = fminf(fmaxf(o.y2, 0.0f),  800.0f);
    return o;
}

// =====================================================================
// K1: one warp per proposal. Softmax over 91 classes, decode fg boxes,
// write masked score, histogram valid scores. (g_hist/g_gcnt zeroed by
// nms_kernel tail on the previous call; static zero-init covers call 1.)
// =====================================================================
__global__ void score_kernel(const float* __restrict__ logits,
                             const float* __restrict__ reg,
                             const float* __restrict__ props) {
    int warp = (blockIdx.x * blockDim.x + threadIdx.x) >> 5;
    int lane = threadIdx.x & 31;
    if (warp >= Bv * Nv) return;

    const float* lrow = logits + (size_t)warp * Cv;
    float l0 = lrow[lane];
    float l1 = lrow[32 + lane];
    float l2 = (64 + lane < Cv) ? lrow[64 + lane] : -3.402823466e38f;
    float m = fmaxf(l0, fmaxf(l1, l2));
    #pragma unroll
    for (int o = 16; o; o >>= 1) m = fmaxf(m, __shfl_xor_sync(0xFFFFFFFFu, m, o));
    float e0 = expf(l0 - m), e1 = expf(l1 - m);
    float e2 = (64 + lane < Cv) ? expf(l2 - m) : 0.0f;
    float s = e0 + e1 + e2;
    #pragma unroll
    for (int o = 16; o; o >>= 1) s += __shfl_xor_sync(0xFFFFFFFFu, s, o);

    int b = warp / Nv, p = warp % Nv;
    const float* pb = props + (size_t)warp * 4;
    float px1 = pb[0], py1 = pb[1], px2 = pb[2], py2 = pb[3];

    float* outsc = g_scores + (size_t)b * NIMG + (size_t)p * FG;
    const float* rrow = reg + (size_t)warp * REGW;

    float ev[3] = {e0, e1, e2};
    #pragma unroll
    for (int k = 0; k < 3; k++) {
        int c = lane + 32 * k;
        if (c >= 1 && c <= FG) {
            float sc = ev[k] / s;
            float4 r = *reinterpret_cast<const float4*>(rrow + c * 4);
            Box bx = decode_one(r, px1, py1, px2, py2);
            float ws = bx.x2 - bx.x1, hs = bx.y2 - bx.y1;
            bool valid = (sc > 0.05f) && (ws >= 0.01f) && (hs >= 0.01f);
            float msc = valid ? sc : -1.0f;
            outsc[c - 1] = msc;
            if (valid) {
                unsigned bin = (orderf(msc) >> 16) - HBASE;
                if (bin < NBINS)
                    atomicAdd(&g_hist[b * NBINS + bin], 1u);
            }
        }
    }
}

// =====================================================================
// K2: gather (wide grid). Each block recomputes the threshold with a
// parallel suffix scan, then gathers composite keys (score,~idx) with
// bin >= thr using warp-aggregated atomics.
// =====================================================================
__global__ void __launch_bounds__(256) gather_kernel() {
    __shared__ unsigned scanA[256], scanB[256];
    __shared__ unsigned sthr;
    int b   = blockIdx.x >> 7;
    int bi  = blockIdx.x & 127;
    int tid = threadIdx.x;
    int lane = tid & 31;
    const unsigned* h = g_hist + b * NBINS;

    {
        unsigned ssum = 0;
        int base = tid * 16;
        #pragma unroll
        for (int j = 0; j < 16; j++) ssum += h[base + j];
        scanA[tid] = ssum;
    }
    __syncthreads();
    unsigned* src = scanA; unsigned* dst = scanB;
    for (int off = 1; off < 256; off <<= 1) {
        dst[tid] = src[tid] + ((tid + off < 256) ? src[tid + off] : 0u);
        __syncthreads();
        unsigned* t = src; src = dst; dst = t;
    }
    {
        unsigned Sc  = src[tid];
        unsigned Sc1 = (tid < 255) ? src[tid + 1] : 0u;
        if (Sc >= TOPK && Sc1 < TOPK) {
            unsigned acc = Sc1;
            int bin = tid * 16 + 15;
            for (; bin >= tid * 16; bin--) {
                acc += h[bin];
                if (acc >= TOPK) break;
            }
            sthr = (unsigned)(bin >= tid * 16 ? bin : tid * 16) + HBASE;
        }
        if (tid == 0 && src[0] < TOPK) sthr = HBASE;
    }
    __syncthreads();
    unsigned thr = sthr;

    const float4* sc4 = reinterpret_cast<const float4*>(g_scores + (size_t)b * NIMG);
    for (int base4 = bi * 256; base4 < NIMG / 4; base4 += 128 * 256) {
        int i4 = base4 + tid;
        bool inb = (i4 < NIMG / 4);
        float4 v = inb ? sc4[i4] : make_float4(-1.f, -1.f, -1.f, -1.f);
        float vs[4] = {v.x, v.y, v.z, v.w};
        #pragma unroll
        for (int c = 0; c < 4; c++) {
            unsigned u = orderf(vs[c]);
            bool hit = inb && ((u >> 16) >= thr);
            unsigned mk = __ballot_sync(0xFFFFFFFFu, hit);
            if (mk) {
                int leader = __ffs(mk) - 1;
                unsigned basep = 0;
                if (lane == leader) basep = atomicAdd(&g_gcnt[b], (unsigned)__popc(mk));
                basep = __shfl_sync(0xFFFFFFFFu, basep, leader);
                if (hit) {
                    unsigned pos = basep + __popc(mk & ((1u << lane) - 1u));
                    unsigned i = (unsigned)(i4 * 4 + c);
                    if (pos < GCAP)
                        g_cand[(size_t)b * GCAP + pos] =
                            ((u64)u << 32) | (u64)(0xFFFFFFFFu - i);
                }
            }
        }
    }
}

// =====================================================================
// K3: fused select + sort + decode + per-class NMS + emit. One block
// per image. Selection exploits g_hist as radix levels 7+6: keys with
// top16 > thr16 are in the top-2048 outright (A of them); a 6-level
// radix select over only the B keys with top16 == thr16 finds the
// exact boundary key. Identical selected set / ordering as before.
// =====================================================================
__global__ void __launch_bounds__(1024, 1) nms_kernel(const float* __restrict__ reg,
                                                      const float* __restrict__ props,
                                                      float* __restrict__ out) {
    extern __shared__ char dyn[];             // 128KB dynamic
    // phase A view (equal-bin keys):
    u64* skeys = reinterpret_cast<u64*>(dyn);                 // [GCAP]
    // phase B+ views (valid after select done):
    float4* cbox  = reinterpret_cast<float4*>(dyn);           // 32KB clipped boxes
    float4* obox  = reinterpret_cast<float4*>(dyn + 32768);   // 32KB offset boxes
    float*  area  = reinterpret_cast<float*>(dyn + 65536);    // 8KB offset-box areas
    float*  ssc   = reinterpret_cast<float*>(dyn + 73728);    // 8KB scores
    int*    slab  = reinterpret_cast<int*>(dyn + 81920);      // 8KB labels
    unsigned short* clsbuf = reinterpret_cast<unsigned short*>(dyn + 90112); // 4KB

    __shared__ u64 sk2[TOPK];                 // 16KB selected keys (then sorted)
    __shared__ unsigned hist[256];
    __shared__ unsigned scanA[256], scanB[256];
    __shared__ unsigned cnts[128], sincl[128];
    __shared__ unsigned char sup8[TOPK];
    __shared__ u64 keepw[32];
    __shared__ float sred[33];
    __shared__ u64 sh_pref;
    __shared__ unsigned sh_k, posA, posB, posC;
    __shared__ int sh_chunk;
    __shared__ unsigned sh_chunkSn, sh_thr16;

    int b = blockIdx.x, tid = threadIdx.x;
    int wid = tid >> 5, lane = tid & 31;
    unsigned cnt = g_gcnt[b];
    if (cnt > GCAP) cnt = GCAP;

    if (tid < 32) keepw[tid] = 0ull;
    if (tid < 128) cnts[tid] = 0u;
    for (int r = tid; r < TOPK; r += 1024) sup8[r] = 0;
    if (tid == 0) { sh_pref = 0ull; sh_k = 0; posA = 0; posB = 0; posC = 0; sh_chunk = -1; }

    // ---- thr16 from g_hist: chunk sums + single-warp shfl suffix scan ----
    if (tid < 256) {
        const unsigned* h = g_hist + b * NBINS + tid * 16;
        unsigned s = 0;
        #pragma unroll
        for (int j = 0; j < 16; j++) s += h[j];
        scanA[tid] = s;
    }
    __syncthreads();
    if (tid < 32) {
        unsigned v[8], tot = 0;
        #pragma unroll
        for (int j = 0; j < 8; j++) { v[j] = scanA[tid * 8 + j]; tot += v[j]; }
        unsigned x = tot;
        #pragma unroll
        for (int off = 1; off < 32; off <<= 1) {
            unsigned y = __shfl_down_sync(0xFFFFFFFFu, x, off);
            if (tid + off < 32) x += y;
        }
        unsigned acc = x - tot;           // sum of chunks > this lane's range
        #pragma unroll
        for (int j = 7; j >= 0; j--) {
            unsigned Sn = acc;
            acc += v[j];
            if (acc >= TOPK && Sn < TOPK) { sh_chunk = tid * 8 + j; sh_chunkSn = Sn; }
        }
    }
    __syncthreads();
    if (tid == 0) {
        int c = sh_chunk;
        if (c < 0) sh_thr16 = HBASE;      // fewer than TOPK valid
        else {
            unsigned acc = sh_chunkSn;
            int bin = c * 16 + 15;
            for (; bin >= c * 16; bin--) {
                acc += g_hist[b * NBINS + bin];
                if (acc >= TOPK) break;
            }
            sh_thr16 = (unsigned)(bin >= c * 16 ? bin : c * 16) + HBASE;
        }
    }
    __syncthreads();
    unsigned thr16 = sh_thr16;

    // ---- stage keys: above -> sk2, equal -> skeys (ballot-aggregated) ----
    for (unsigned i0 = 0; i0 < cnt; i0 += 1024) {
        unsigned i = i0 + tid;
        bool inb = (i < cnt);
        u64 key = inb ? g_cand[(size_t)b * GCAP + i] : 0ull;
        unsigned top16 = (unsigned)(key >> 48);
        bool above = inb && (top16 > thr16);
        bool equal = inb && (top16 == thr16);
        unsigned mA = __ballot_sync(0xFFFFFFFFu, above);
        if (mA) {
            int leader = __ffs(mA) - 1;
            unsigned basep = 0;
            if (lane == leader) basep = atomicAdd(&posA, (unsigned)__popc(mA));
            basep = __shfl_sync(0xFFFFFFFFu, basep, leader);
            if (above) {
                unsigned pos = basep + __popc(mA & ((1u << lane) - 1u));
                if (pos < TOPK) sk2[pos] = key;
            }
        }
        unsigned mB = __ballot_sync(0xFFFFFFFFu, equal);
        if (mB) {
            int leader = __ffs(mB) - 1;
            unsigned basep = 0;
            if (lane == leader) basep = atomicAdd(&posB, (unsigned)__popc(mB));
            basep = __shfl_sync(0xFFFFFFFFu, basep, leader);
            if (equal) skeys[basep + __popc(mB & ((1u << lane) - 1u))] = key;
        }
    }
    __syncthreads();
    unsigned A = posA, B = posB;

    if (A + B > TOPK) {
        // ---- radix select among equals: 6 levels on low 48 bits ----
        if (tid == 0) { sh_pref = (u64)thr16; sh_k = TOPK - A; }
        __syncthreads();
        for (int level = 5; level >= 0; level--) {
            int shift = level * 8;
            if (tid < 256) hist[tid] = 0;
            __syncthreads();
            u64 pref = sh_pref;
            unsigned k = sh_k;
            for (unsigned i = tid; i < B; i += 1024) {
                u64 key = skeys[i];
                if ((key >> (shift + 8)) == pref)
                    atomicAdd(&hist[(unsigned)(key >> shift) & 0xFFu], 1u);
            }
            __syncthreads();
            if (tid < 32) {
                unsigned v[8], tot = 0;
                #pragma unroll
                for (int j = 0; j < 8; j++) { v[j] = hist[tid * 8 + j]; tot += v[j]; }
                unsigned x = tot;
                #pragma unroll
                for (int off = 1; off < 32; off <<= 1) {
                    unsigned y = __shfl_down_sync(0xFFFFFFFFu, x, off);
                    if (tid + off < 32) x += y;
                }
                unsigned acc = x - tot;
                #pragma unroll
                for (int j = 7; j >= 0; j--) {
                    unsigned Sn = acc;
                    acc += v[j];
                    if (acc >= k && Sn < k) {
                        sh_pref = (pref << 8) | (u64)(unsigned)(tid * 8 + j);
                        sh_k = k - Sn;
                    }
                }
            }
            __syncthreads();
        }
        u64 kstar = sh_pref;
        // ---- compact equals >= kstar (exactly TOPK - A by uniqueness) ----
        for (unsigned i0 = 0; i0 < B; i0 += 1024) {
            unsigned i = i0 + tid;
            bool hit = (i < B) && (skeys[i] >= kstar);
            unsigned mk = __ballot_sync(0xFFFFFFFFu, hit);
            if (mk) {
                int leader = __ffs(mk) - 1;
                unsigned basep = 0;
                if (lane == leader) basep = atomicAdd(&posC, (unsigned)__popc(mk));
                basep = __shfl_sync(0xFFFFFFFFu, basep, leader);
                if (hit) {
                    unsigned pos = A + basep + __popc(mk & ((1u << lane) - 1u));
                    if (pos < TOPK) sk2[pos] = skeys[i];
                }
            }
        }
    } else {
        for (unsigned i = tid; i < B; i += 1024) sk2[A + i] = skeys[i];
        for (unsigned i = tid; i < TOPK; i += 1024)
            if (i >= A + B) sk2[i] = 0ull;
    }
    __syncthreads();      // dyn region reusable from here

    // ---- bitonic sort 2048 descending ----
    for (unsigned kk = 2; kk <= TOPK; kk <<= 1) {
        for (unsigned j = kk >> 1; j; j >>= 1) {
            for (unsigned i = tid; i < TOPK; i += 1024) {
                unsigned p = i ^ j;
                if (p > i) {
                    bool desc = ((i & kk) == 0);
                    u64 a = sk2[i], c = sk2[p];
                    if (desc ? (a < c) : (a > c)) { sk2[i] = c; sk2[p] = a; }
                }
            }
            __syncthreads();
        }
    }

    // ---- decode sorted top-2048 into smem, block max ----
    float lmax = -3.402823466e38f;
    for (int r = tid; r < TOPK; r += 1024) {
        u64 key = sk2[r];
        unsigned idx = 0xFFFFFFFFu - (unsigned)(key & 0xFFFFFFFFull);
        if (idx >= NIMG) idx = NIMG - 1;     // safety clamp (padding)
        float score = unorderf((unsigned)(key >> 32));
        int p = idx / FG, cls = (int)(idx % FG) + 1;
        const float* pb = props + ((size_t)b * Nv + p) * 4;
        float4 rr = *reinterpret_cast<const float4*>(reg + ((size_t)b * Nv + p) * REGW + cls * 4);
        Box bx = decode_one(rr, pb[0], pb[1], pb[2], pb[3]);
        cbox[r] = make_float4(bx.x1, bx.y1, bx.x2, bx.y2);
        ssc[r]  = score;
        slab[r] = cls;
        atomicAdd(&cnts[cls], 1u);
        lmax = fmaxf(lmax, fmaxf(fmaxf(bx.x1, bx.y1), fmaxf(bx.x2, bx.y2)));
    }
    #pragma unroll
    for (int o = 16; o; o >>= 1) lmax = fmaxf(lmax, __shfl_xor_sync(0xFFFFFFFFu, lmax, o));
    if (lane == 0) sred[wid] = lmax;
    __syncthreads();
    if (tid < 32) {
        float v = sred[tid];
        #pragma unroll
        for (int o = 16; o; o >>= 1) v = fmaxf(v, __shfl_xor_sync(0xFFFFFFFFu, v, o));
        if (tid == 0) sred[32] = v;
    }
    __syncthreads();
    float step = sred[32] + 1.0f;

    // ---- offset boxes + areas (exact reference fp sequence) ----
    for (int r = tid; r < TOPK; r += 1024) {
        float off = (float)slab[r] * step;
        float4 cb = cbox[r];
        float4 ob = make_float4(cb.x + off, cb.y + off, cb.z + off, cb.w + off);
        obox[r] = ob;
        area[r] = (ob.z - ob.x) * (ob.w - ob.y);
    }

    // ---- inclusive scan of class counts (128 entries, Hillis-Steele) ----
    __syncthreads();
    {
        unsigned* src = scanA; unsigned* dst = scanB;
        if (tid < 128) src[tid] = cnts[tid];
        __syncthreads();
        for (int off = 1; off < 128; off <<= 1) {
            if (tid < 128)
                dst[tid] = src[tid] + ((tid >= (unsigned)off) ? src[tid - off] : 0u);
            __syncthreads();
            unsigned* t = src; src = dst; dst = t;
        }
        if (tid < 128) sincl[tid] = src[tid];
    }
    __syncthreads();

    // ---- stable class bucketing: warp per class, ballot compaction ----
    #pragma unroll
    for (int cc = 0; cc < 3; cc++) {
        int c = 1 + wid + cc * 32;
        if (c <= FG) {
            unsigned seg = sincl[c - 1];
            unsigned pos = 0;
            for (int base = 0; base < TOPK; base += 32) {
                int r = base + lane;
                bool hit = (slab[r] == c);
                unsigned mk = __ballot_sync(0xFFFFFFFFu, hit);
                if (hit)
                    clsbuf[seg + pos + __popc(mk & ((1u << lane) - 1u))] = (unsigned short)r;
                pos += __popc(mk);
            }
        }
    }
    __syncthreads();

    // ---- per-class greedy NMS (warp per class) ----
    #pragma unroll
    for (int cc = 0; cc < 3; cc++) {
        int c = 1 + wid + cc * 32;
        if (c <= FG) {
            unsigned seg = sincl[c - 1];
            int n = (int)(sincl[c] - sincl[c - 1]);
            for (int k = 0; k < n; k++) {
                int rk = clsbuf[seg + k];
                bool act = (ssc[rk] > 0.0f) && (sup8[rk] == 0);
                if (act) {
                    float4 bi = obox[rk];
                    float  ai = area[rk];
                    for (int mi = k + 1 + lane; mi < n; mi += 32) {
                        int rm = clsbuf[seg + mi];
                        float4 bj = obox[rm];
                        float  aj = area[rm];
                        float ltx = fmaxf(bi.x, bj.x), lty = fmaxf(bi.y, bj.y);
                        float rbx = fminf(bi.z, bj.z), rby = fminf(bi.w, bj.w);
                        float ww  = fmaxf(rbx - ltx, 0.0f), hh = fmaxf(rby - lty, 0.0f);
                        float inter = ww * hh;
                        float U = (ai + aj) - inter;
                        float hU = 0.5f * U;
                        bool sup;
                        if (inter > hU * 1.000001f)       sup = true;
                        else if (inter < hU * 0.999999f)  sup = false;
                        else                               sup = (inter / U) > 0.5f;
                        if (sup) sup8[rm] = 1;
                    }
                }
                __syncwarp();
            }
        }
    }
    __syncthreads();

    // ---- keep bits ----
    for (int r = tid; r < TOPK; r += 1024) {
        if (ssc[r] > 0.0f && sup8[r] == 0)
            atomicOr(&keepw[r >> 6], 1ull << (r & 63));
    }
    __syncthreads();

    // ---- emission (warp 0): kept in rank order, then non-kept fill ----
    if (wid == 0) {
        u64 keep = keepw[lane];
        int kc  = __popcll(keep);
        int inc = kc;
        #pragma unroll
        for (int o = 1; o < 32; o <<= 1) {
            int v = __shfl_up_sync(0xFFFFFFFFu, inc, o);
            if (lane >= o) inc += v;
        }
        int excl  = inc - kc;
        int total = __shfl_sync(0xFFFFFFFFu, inc, 31);

        float* oboxes  = out;                     // [B,100,4]
        float* oscores = out + Bv * DETS * 4;     // [B,100]
        float* olabels = out + Bv * DETS * 5;     // [B,100]

        for (int k = 0; k < 64; k++) {
            int r = lane * 64 + k;
            u64 below = (k == 0) ? 0ull : (keep & ((1ull << k) - 1ull));
            int kb   = excl + __popcll(below);
            int kp   = (int)((keep >> k) & 1ull);
            int slot = kp ? kb : total + (r - kb);
            if (slot < DETS) {
                float4 cb = cbox[r];
                float* obp = oboxes + ((size_t)b * DETS + slot) * 4;
                obp[0] = cb.x; obp[1] = cb.y; obp[2] = cb.z; obp[3] = cb.w;
                oscores[b * DETS + slot] = kp ? ssc[r] : -1.0f;
                olabels[b * DETS + slot] = (float)slab[r];
            }
        }
    }

    // ---- zero hist/gcnt for next call ----
    for (int i = tid; i < NBINS; i += 1024) g_hist[b * NBINS + i] = 0u;
    if (tid == 0) g_gcnt[b] = 0u;
}

extern "C" void kernel_launch(void* const* d_in, const int* in_sizes, int n_in,
                              void* d_out, int out_size) {
    const float* logits = (const float*)d_in[0];   // [16000, 91]
    const float* reg    = (const float*)d_in[1];   // [16000, 364]
    const float* props  = (const float*)d_in[2];   // [8, 2000, 4]
    float* out = (float*)d_out;

    score_kernel<<<(Bv * Nv + 7) / 8, 256>>>(logits, reg, props);
    gather_kernel<<<Bv * 128, 256>>>();
    cudaFuncSetAttribute(nms_kernel, cudaFuncAttributeMaxDynamicSharedMemorySize,
                         GCAP * (int)sizeof(u64));
    nms_kernel<<<Bv, 1024, GCAP * sizeof(u64)>>>(reg, props, out);
}